// round 6
// baseline (speedup 1.0000x reference)
#include <cuda_runtime.h>
#include <math.h>

#define N_FFT   1024
#define HOP     256
#define NBINS   513
#define NMELS   128
#define BATCH   32
#define SIGLEN  160000
#define PAD     512
#define NFRAMES 626
#define SUP     26
#define FPB     8              // frames per block
#define NFBLK   79             // ceil(626/8)
#define NFBLK_A 40             // split for profiling (pos 3)
#define NFBLK_B 39             // split for profiling (pos 4)
#define CFFT    4              // complex FFTs per block (2 frames each)
#define MPITCH  33
#define MSZ     (32 * MPITCH)  // 1056 floats per matrix

#define KCH     32             // EMA chunks per chain
#define LCH     20             // frames per chunk
#define EMA_A   0.975f
#define EMA_S   0.025f

// ---------------- device scratch ----------------
__device__ float  g_mel[BATCH * NFRAMES * NMELS];
__device__ float  g_T  [BATCH * KCH * NMELS];      // zero-init; chunk 31 stays 0
__device__ float  g_Sin[BATCH * KCH * NMELS];
__device__ float  g_fbT[SUP * NMELS];
__device__ int    g_start[NMELS];
__device__ float2 g_tw[N_FFT];                     // exp(-2*pi*i*k/1024)

// ---------------- prep A: twiddles ----------------
__global__ void prep_tw_kernel() {
    int k = blockIdx.x * 256 + threadIdx.x;        // grid 4 -> 0..1023
    float ang = -6.283185307179586f * (float)k / (float)N_FFT;
    float s, c;
    sincosf(ang, &s, &c);
    g_tw[k] = make_float2(c, s);
}

// ---------------- prep B: fb compaction, one warp per mel ---------------
__global__ void prep_fb_kernel(const float* __restrict__ fb) {
    const int m    = blockIdx.x;
    const int lane = threadIdx.x;

    int first = 0x7fffffff, last = -1;
    for (int f = lane; f < NBINS; f += 32) {
        float v = fb[f * NMELS + m];
        if (v != 0.0f) { first = min(first, f); last = max(last, f); }
    }
    first = __reduce_min_sync(0xffffffffu, first);
    last  = __reduce_max_sync(0xffffffffu, last);

    int st  = (last < 0) ? 0 : first;
    int len = (last < 0) ? 0 : (last - first + 1);
    if (len > SUP) len = SUP;

    if (lane == 0) g_start[m] = st;
    if (lane < SUP) {
        int j = lane;
        g_fbT[j * NMELS + m] = (j < len) ? fb[(st + j) * NMELS + m] : 0.0f;
    }
}

// ---------------- in-register FFT32 helpers ----------------
__host__ __device__ constexpr int brev5(int i) {
    return ((i & 1) << 4) | ((i & 2) << 2) | (i & 4) | ((i & 8) >> 2) | ((i & 16) >> 4);
}
__device__ __forceinline__ constexpr float w32r(int j) {
    return (j == 0) ?  1.0f :
           (j == 1) ?  0.980785280403230f :
           (j == 2) ?  0.923879532511287f :
           (j == 3) ?  0.831469612302545f :
           (j == 4) ?  0.707106781186548f :
           (j == 5) ?  0.555570233019602f :
           (j == 6) ?  0.382683432365090f :
           (j == 7) ?  0.195090322016128f :
           (j == 8) ?  0.0f :
           (j == 9) ? -0.195090322016128f :
           (j ==10) ? -0.382683432365090f :
           (j ==11) ? -0.555570233019602f :
           (j ==12) ? -0.707106781186548f :
           (j ==13) ? -0.831469612302545f :
           (j ==14) ? -0.923879532511287f :
                      -0.980785280403230f;
}
__device__ __forceinline__ constexpr float w32i(int j) {
    return (j == 0) ?  0.0f :
           (j == 1) ? -0.195090322016128f :
           (j == 2) ? -0.382683432365090f :
           (j == 3) ? -0.555570233019602f :
           (j == 4) ? -0.707106781186548f :
           (j == 5) ? -0.831469612302545f :
           (j == 6) ? -0.923879532511287f :
           (j == 7) ? -0.980785280403230f :
           (j == 8) ? -1.0f :
           (j == 9) ? -0.980785280403230f :
           (j ==10) ? -0.923879532511287f :
           (j ==11) ? -0.831469612302545f :
           (j ==12) ? -0.707106781186548f :
           (j ==13) ? -0.555570233019602f :
           (j ==14) ? -0.382683432365090f :
                      -0.195090322016128f;
}

// input in bit-reversed order, output natural order
__device__ __forceinline__ void fft32(float xr[32], float xi[32]) {
    #pragma unroll
    for (int s = 0; s < 5; s++) {
        const int half = 1 << s;
        #pragma unroll
        for (int g = 0; g < (16 >> s); g++) {
            #pragma unroll
            for (int j = 0; j < half; j++) {
                const int i1 = g * 2 * half + j;
                const int i2 = i1 + half;
                const float wr = w32r(j << (4 - s));
                const float wi = w32i(j << (4 - s));
                float tr = xr[i2] * wr - xi[i2] * wi;
                float ti = xr[i2] * wi + xi[i2] * wr;
                xr[i2] = xr[i1] - tr;  xi[i2] = xi[i1] - ti;
                xr[i1] += tr;          xi[i1] += ti;
            }
        }
    }
}

__device__ __forceinline__ int reflect_idx(int src) {
    if (src < 0) src = -src;
    if (src >= SIGLEN) src = 2 * SIGLEN - 2 - src;
    return src;
}

// ---------------- fft + mel: 32x32 two-pass register FFT ----------------
__global__ __launch_bounds__(128)
void fft_mel_kernel(const float* __restrict__ x, int fblk_off) {
    __shared__ float Sre[CFFT * MSZ];   // 16.9 KB
    __shared__ float Sim[CFFT * MSZ];   // 16.9 KB

    const int tid   = threadIdx.x;
    const int q     = tid >> 5;         // cFFT index 0..3
    const int ln    = tid & 31;         // lane
    const int b     = blockIdx.y;
    const int fbase = (blockIdx.x + fblk_off) * FPB;

    const float* xb = x + (size_t)b * SIGLEN;
    float* mre = Sre + q * MSZ;
    float* mim = Sim + q * MSZ;

    // ---- load frames (2q, 2q+1) packed as re/im, layout M[n2][n1] ----
    const int baseA = (fbase + 2 * q) * HOP - PAD;
    const int baseB = baseA + HOP;
    if (baseA >= 0 && baseB + N_FFT <= SIGLEN) {
        #pragma unroll
        for (int j = 0; j < 32; j++) {
            int n = ln + 32 * j;
            mre[MPITCH * j + ln] = xb[baseA + n];
            mim[MPITCH * j + ln] = xb[baseB + n];
        }
    } else {
        #pragma unroll 4
        for (int j = 0; j < 32; j++) {
            int n = ln + 32 * j;
            mre[MPITCH * j + ln] = xb[reflect_idx(baseA + n)];
            mim[MPITCH * j + ln] = xb[reflect_idx(baseB + n)];
        }
    }
    __syncwarp();

    float xr[32], xi[32];

    // ---- pass 1: FFT32 over n2 (this thread = column n1 = ln) ----
    #pragma unroll
    for (int i = 0; i < 32; i++) {
        const int r = brev5(i);
        xr[i] = mre[MPITCH * r + ln];
        xi[i] = mim[MPITCH * r + ln];
    }
    fft32(xr, xi);

    // ---- twiddle W^{ln*k2} computed incrementally in registers ----
    // w_{k2+1} = w_{k2} * W^ln; refresh from the table every 8 steps
    {
        const float2 step = g_tw[ln];
        float2 w = make_float2(1.0f, 0.0f);
        #pragma unroll
        for (int k2 = 0; k2 < 32; k2++) {
            if (k2 == 8 || k2 == 16 || k2 == 24)
                w = g_tw[(k2 * ln) & (N_FFT - 1)];
            float tr = xr[k2] * w.x - xi[k2] * w.y;
            float ti = xr[k2] * w.y + xi[k2] * w.x;
            mre[MPITCH * k2 + ln] = tr;
            mim[MPITCH * k2 + ln] = ti;
            float nwx = w.x * step.x - w.y * step.y;
            float nwy = w.x * step.y + w.y * step.x;
            w = make_float2(nwx, nwy);
        }
    }
    __syncwarp();

    // ---- pass 2: FFT32 over n1 (this thread = row k2 = ln) ----
    #pragma unroll
    for (int i = 0; i < 32; i++) {
        const int r = brev5(i);
        xr[i] = mre[MPITCH * ln + r];
        xi[i] = mim[MPITCH * ln + r];
    }
    __syncwarp();          // all lanes done reading M before spec overlay
    fft32(xr, xi);         // now xr/xi[k1] = X[ln + 32*k1]

    // ---- conjugate unpack via shuffles, spec overlays M region ----
    float* sA = mre;       // spec frame A: [0..512] + pad [513..538]
    float* sB = mim;
    const int lnp = (32 - ln) & 31;
    #pragma unroll
    for (int k1 = 0; k1 < 16; k1++) {
        float pr = __shfl_sync(0xffffffffu, xr[31 - k1], lnp);
        float pi = __shfl_sync(0xffffffffu, xi[31 - k1], lnp);
        if (ln == 0) { pr = xr[(32 - k1) & 31]; pi = xi[(32 - k1) & 31]; }
        float ar = 0.5f * (xr[k1] + pr), ai = 0.5f * (xi[k1] - pi);
        float br = 0.5f * (xi[k1] + pi), bi = 0.5f * (pr - xr[k1]);
        sA[ln + 32 * k1] = sqrtf(ar * ar + ai * ai);
        sB[ln + 32 * k1] = sqrtf(br * br + bi * bi);
    }
    if (ln == 0) { sA[512] = fabsf(xr[16]); sB[512] = fabsf(xi[16]); }
    if (ln < SUP) { sA[513 + ln] = 0.0f; sB[513 + ln] = 0.0f; }
    __syncthreads();       // the only block-wide barrier

    // ---- sparse mel: thread = mel channel, all 8 frames ----
    {
        const int m  = tid;
        const int st = g_start[m];
        float acc[FPB];
        #pragma unroll
        for (int f = 0; f < FPB; f++) acc[f] = 0.0f;
        #pragma unroll
        for (int j = 0; j < SUP; j++) {
            float fv = g_fbT[j * NMELS + m];
            #pragma unroll
            for (int f = 0; f < FPB; f++) {
                const float* sp = ((f & 1) ? Sim : Sre) + (f >> 1) * MSZ;
                acc[f] += sp[st + j] * fv;
            }
        }
        #pragma unroll
        for (int f = 0; f < FPB; f++) {
            int frame = fbase + f;
            if (frame < NFRAMES)
                g_mel[((size_t)b * NFRAMES + frame) * NMELS + m] = acc[f];
        }
    }
}

// ---------------- PCEN stage 1: per-chunk partial EMA (c = 0..30) -------
__global__ __launch_bounds__(128)
void pcen_part1_kernel() {
    const int m = threadIdx.x;
    const int b = blockIdx.x;
    const int c = blockIdx.y;          // 0..KCH-2 (all full chunks)

    const float* p = g_mel + ((size_t)b * NFRAMES + c * LCH) * NMELS + m;

    float state;
    if (c == 0) {
        state = p[0];
        #pragma unroll
        for (int t = 1; t < LCH; t++) {
            float v = p[(size_t)t * NMELS];
            state = fmaf(EMA_A, state, EMA_S * v);
        }
    } else {
        state = 0.0f;
        #pragma unroll
        for (int t = 0; t < LCH; t++) {
            float v = p[(size_t)t * NMELS];
            state = fmaf(EMA_A, state, EMA_S * v);
        }
    }
    g_T[((size_t)b * KCH + c) * NMELS + m] = state;
}

// ---------------- PCEN stage 2: serial chunk prefix ---------------------
__global__ __launch_bounds__(128)
void pcen_combine_kernel() {
    const int m = threadIdx.x;
    const int b = blockIdx.x;

    float Tv[KCH];
    #pragma unroll
    for (int c = 0; c < KCH; c++)
        Tv[c] = g_T[((size_t)b * KCH + c) * NMELS + m];

    float A = 1.0f;
    #pragma unroll
    for (int i = 0; i < LCH; i++) A *= EMA_A;

    float S = 0.0f;
    #pragma unroll
    for (int c = 0; c < KCH; c++) {
        g_Sin[((size_t)b * KCH + c) * NMELS + m] = S;
        S = fmaf(A, S, Tv[c]);
    }
}

// ---------------- PCEN stage 3: outputs ----------------------------------
__device__ __forceinline__ float pcen_f(float v, float M) {
    float pw = exp2f(-0.98f * __log2f(M + 1e-6f));     // (M+eps)^-0.98
    float y  = fmaf(v, pw, 2.0f);
    return y * rsqrtf(y) - 1.41421356237309515f;       // sqrt(y) - sqrt(2)
}

__global__ __launch_bounds__(128)
void pcen_part2_kernel(float* __restrict__ out) {
    const int m = threadIdx.x;
    const int b = blockIdx.x;
    const int c = blockIdx.y;

    const int t0 = c * LCH;
    const float* p = g_mel + ((size_t)b * NFRAMES + t0) * NMELS + m;
    float*       o = out  + ((size_t)b * NFRAMES + t0) * NMELS + m;

    if (c == 0) {
        float v0 = p[0];
        float state = v0;
        o[0] = pcen_f(v0, state);
        #pragma unroll
        for (int t = 1; t < LCH; t++) {
            float v = p[(size_t)t * NMELS];
            state = fmaf(EMA_A, state, EMA_S * v);
            o[(size_t)t * NMELS] = pcen_f(v, state);
        }
    } else if (c < KCH - 1) {
        float state = g_Sin[((size_t)b * KCH + c) * NMELS + m];
        #pragma unroll
        for (int t = 0; t < LCH; t++) {
            float v = p[(size_t)t * NMELS];
            state = fmaf(EMA_A, state, EMA_S * v);
            o[(size_t)t * NMELS] = pcen_f(v, state);
        }
    } else {
        float state = g_Sin[((size_t)b * KCH + c) * NMELS + m];
        #pragma unroll
        for (int t = 0; t < NFRAMES - (KCH - 1) * LCH; t++) {   // 6 frames
            float v = p[(size_t)t * NMELS];
            state = fmaf(EMA_A, state, EMA_S * v);
            o[(size_t)t * NMELS] = pcen_f(v, state);
        }
    }
}

// ---------------- launch ----------------
extern "C" void kernel_launch(void* const* d_in, const int* in_sizes, int n_in,
                              void* d_out, int out_size) {
    const float* x  = (const float*)d_in[0];   // (32, 160000) f32
    const float* fb = (const float*)d_in[1];   // (513, 128)  f32
    float* out = (float*)d_out;                // (32, 626, 128) f32

    prep_tw_kernel<<<4, 256>>>();
    prep_fb_kernel<<<NMELS, 32>>>(fb);
    // fft_mel split in two: the 4th launch is the one ncu captures
    fft_mel_kernel<<<dim3(NFBLK_A, BATCH), 128>>>(x, 0);
    fft_mel_kernel<<<dim3(NFBLK_B, BATCH), 128>>>(x, NFBLK_A);
    pcen_part1_kernel<<<dim3(BATCH, KCH - 1), 128>>>();
    pcen_combine_kernel<<<BATCH, 128>>>();
    pcen_part2_kernel<<<dim3(BATCH, KCH), 128>>>(out);
}

// round 7
// speedup vs baseline: 1.0213x; 1.0213x over previous
#include <cuda_runtime.h>
#include <math.h>

#define N_FFT   1024
#define HOP     256
#define NBINS   513
#define NMELS   128
#define BATCH   32
#define SIGLEN  160000
#define PAD     512
#define NFRAMES 626
#define SUP     26
#define FPB     8              // frames per block
#define NFBLK   79             // ceil(626/8)
#define NFBLK_A 40             // split for profiling (pos 3)
#define NFBLK_B 39             // split for profiling (pos 4)
#define CFFT    4              // complex FFTs per block (2 frames each)
#define MPITCH  33
#define MSZ     (32 * MPITCH)  // 1056 floats per matrix

#define KCH     32             // EMA chunks per chain
#define LCH     20             // frames per chunk
#define EMA_A   0.975f
#define EMA_S   0.025f

// ---------------- device scratch ----------------
__device__ float  g_mel[BATCH * NFRAMES * NMELS];
__device__ float  g_T  [BATCH * KCH * NMELS];
__device__ float  g_Sin[BATCH * KCH * NMELS];
__device__ float  g_fbT[SUP * NMELS];
__device__ int    g_start[NMELS];
__device__ float2 g_tw[N_FFT];                     // exp(-2*pi*i*k/1024)

// ---------------- prep A: twiddles ----------------
__global__ void prep_tw_kernel() {
    int k = blockIdx.x * 256 + threadIdx.x;        // grid 4 -> 0..1023
    float ang = -6.283185307179586f * (float)k / (float)N_FFT;
    float s, c;
    sincosf(ang, &s, &c);
    g_tw[k] = make_float2(c, s);
}

// ---------------- prep B: fb compaction, one warp per mel ---------------
__global__ void prep_fb_kernel(const float* __restrict__ fb) {
    const int m    = blockIdx.x;
    const int lane = threadIdx.x;

    int first = 0x7fffffff, last = -1;
    for (int f = lane; f < NBINS; f += 32) {
        float v = fb[f * NMELS + m];
        if (v != 0.0f) { first = min(first, f); last = max(last, f); }
    }
    first = __reduce_min_sync(0xffffffffu, first);
    last  = __reduce_max_sync(0xffffffffu, last);

    int st  = (last < 0) ? 0 : first;
    int len = (last < 0) ? 0 : (last - first + 1);
    if (len > SUP) len = SUP;

    if (lane == 0) g_start[m] = st;
    if (lane < SUP) {
        int j = lane;
        g_fbT[j * NMELS + m] = (j < len) ? fb[(st + j) * NMELS + m] : 0.0f;
    }
}

// ---------------- in-register FFT32 helpers ----------------
__host__ __device__ constexpr int brev5(int i) {
    return ((i & 1) << 4) | ((i & 2) << 2) | (i & 4) | ((i & 8) >> 2) | ((i & 16) >> 4);
}
__device__ __forceinline__ constexpr float w32r(int j) {
    return (j == 0) ?  1.0f :
           (j == 1) ?  0.980785280403230f :
           (j == 2) ?  0.923879532511287f :
           (j == 3) ?  0.831469612302545f :
           (j == 4) ?  0.707106781186548f :
           (j == 5) ?  0.555570233019602f :
           (j == 6) ?  0.382683432365090f :
           (j == 7) ?  0.195090322016128f :
           (j == 8) ?  0.0f :
           (j == 9) ? -0.195090322016128f :
           (j ==10) ? -0.382683432365090f :
           (j ==11) ? -0.555570233019602f :
           (j ==12) ? -0.707106781186548f :
           (j ==13) ? -0.831469612302545f :
           (j ==14) ? -0.923879532511287f :
                      -0.980785280403230f;
}
__device__ __forceinline__ constexpr float w32i(int j) {
    return (j == 0) ?  0.0f :
           (j == 1) ? -0.195090322016128f :
           (j == 2) ? -0.382683432365090f :
           (j == 3) ? -0.555570233019602f :
           (j == 4) ? -0.707106781186548f :
           (j == 5) ? -0.831469612302545f :
           (j == 6) ? -0.923879532511287f :
           (j == 7) ? -0.980785280403230f :
           (j == 8) ? -1.0f :
           (j == 9) ? -0.980785280403230f :
           (j ==10) ? -0.923879532511287f :
           (j ==11) ? -0.831469612302545f :
           (j ==12) ? -0.707106781186548f :
           (j ==13) ? -0.555570233019602f :
           (j ==14) ? -0.382683432365090f :
                      -0.195090322016128f;
}

// input in bit-reversed order, output natural order
__device__ __forceinline__ void fft32(float xr[32], float xi[32]) {
    #pragma unroll
    for (int s = 0; s < 5; s++) {
        const int half = 1 << s;
        #pragma unroll
        for (int g = 0; g < (16 >> s); g++) {
            #pragma unroll
            for (int j = 0; j < half; j++) {
                const int i1 = g * 2 * half + j;
                const int i2 = i1 + half;
                const float wr = w32r(j << (4 - s));
                const float wi = w32i(j << (4 - s));
                float tr = xr[i2] * wr - xi[i2] * wi;
                float ti = xr[i2] * wi + xi[i2] * wr;
                xr[i2] = xr[i1] - tr;  xi[i2] = xi[i1] - ti;
                xr[i1] += tr;          xi[i1] += ti;
            }
        }
    }
}

__device__ __forceinline__ int reflect_idx(int src) {
    if (src < 0) src = -src;
    if (src >= SIGLEN) src = 2 * SIGLEN - 2 - src;
    return src;
}

// ---------------- fft + mel: 32x32 two-pass register FFT ----------------
// launch_bounds(128, 1): allow ptxas up to 255 regs -- the 64-float FFT
// register arrays MUST stay in registers (R6 spilled at regs=80).
__global__ __launch_bounds__(128, 1)
void fft_mel_kernel(const float* __restrict__ x, int fblk_off) {
    __shared__ float Sre[CFFT * MSZ];   // 16.9 KB
    __shared__ float Sim[CFFT * MSZ];   // 16.9 KB

    const int tid   = threadIdx.x;
    const int q     = tid >> 5;         // cFFT index 0..3
    const int ln    = tid & 31;         // lane
    const int b     = blockIdx.y;
    const int fbase = (blockIdx.x + fblk_off) * FPB;

    const float* xb = x + (size_t)b * SIGLEN;
    float* mre = Sre + q * MSZ;
    float* mim = Sim + q * MSZ;

    // ---- load frames (2q, 2q+1) packed as re/im, layout M[n2][n1] ----
    const int baseA = (fbase + 2 * q) * HOP - PAD;
    const int baseB = baseA + HOP;
    if (baseA >= 0 && baseB + N_FFT <= SIGLEN) {
        #pragma unroll
        for (int j = 0; j < 32; j++) {
            int n = ln + 32 * j;
            mre[MPITCH * j + ln] = xb[baseA + n];
            mim[MPITCH * j + ln] = xb[baseB + n];
        }
    } else {
        #pragma unroll 4
        for (int j = 0; j < 32; j++) {
            int n = ln + 32 * j;
            mre[MPITCH * j + ln] = xb[reflect_idx(baseA + n)];
            mim[MPITCH * j + ln] = xb[reflect_idx(baseB + n)];
        }
    }
    __syncwarp();

    float xr[32], xi[32];

    // ---- pass 1: FFT32 over n2 (this thread = column n1 = ln) ----
    #pragma unroll
    for (int i = 0; i < 32; i++) {
        const int r = brev5(i);
        xr[i] = mre[MPITCH * r + ln];
        xi[i] = mim[MPITCH * r + ln];
    }
    fft32(xr, xi);

    // ---- twiddle W^{ln*k2} purely incremental in registers ----
    // drift over 31 cmuls ~ a few ulp: irrelevant vs 1e-3 tolerance
    {
        const float2 step = g_tw[ln];
        float2 w = make_float2(1.0f, 0.0f);
        #pragma unroll
        for (int k2 = 0; k2 < 32; k2++) {
            float tr = xr[k2] * w.x - xi[k2] * w.y;
            float ti = xr[k2] * w.y + xi[k2] * w.x;
            mre[MPITCH * k2 + ln] = tr;
            mim[MPITCH * k2 + ln] = ti;
            float nwx = w.x * step.x - w.y * step.y;
            float nwy = w.x * step.y + w.y * step.x;
            w = make_float2(nwx, nwy);
        }
    }
    __syncwarp();

    // ---- pass 2: FFT32 over n1 (this thread = row k2 = ln) ----
    #pragma unroll
    for (int i = 0; i < 32; i++) {
        const int r = brev5(i);
        xr[i] = mre[MPITCH * ln + r];
        xi[i] = mim[MPITCH * ln + r];
    }
    __syncwarp();          // all lanes done reading M before spec overlay
    fft32(xr, xi);         // now xr/xi[k1] = X[ln + 32*k1]

    // ---- conjugate unpack via shuffles, spec overlays M region ----
    float* sA = mre;       // spec frame A: [0..512] + pad [513..538]
    float* sB = mim;
    const int lnp = (32 - ln) & 31;
    #pragma unroll
    for (int k1 = 0; k1 < 16; k1++) {
        float pr = __shfl_sync(0xffffffffu, xr[31 - k1], lnp);
        float pi = __shfl_sync(0xffffffffu, xi[31 - k1], lnp);
        if (ln == 0) { pr = xr[(32 - k1) & 31]; pi = xi[(32 - k1) & 31]; }
        float ar = 0.5f * (xr[k1] + pr), ai = 0.5f * (xi[k1] - pi);
        float br = 0.5f * (xi[k1] + pi), bi = 0.5f * (pr - xr[k1]);
        sA[ln + 32 * k1] = sqrtf(ar * ar + ai * ai);
        sB[ln + 32 * k1] = sqrtf(br * br + bi * bi);
    }
    if (ln == 0) { sA[512] = fabsf(xr[16]); sB[512] = fabsf(xi[16]); }
    if (ln < SUP) { sA[513 + ln] = 0.0f; sB[513 + ln] = 0.0f; }
    __syncthreads();       // the only block-wide barrier

    // ---- sparse mel: thread = mel channel, all 8 frames ----
    {
        const int m  = tid;
        const int st = g_start[m];
        float acc[FPB];
        #pragma unroll
        for (int f = 0; f < FPB; f++) acc[f] = 0.0f;
        #pragma unroll
        for (int j = 0; j < SUP; j++) {
            float fv = g_fbT[j * NMELS + m];
            #pragma unroll
            for (int f = 0; f < FPB; f++) {
                const float* sp = ((f & 1) ? Sim : Sre) + (f >> 1) * MSZ;
                acc[f] += sp[st + j] * fv;
            }
        }
        #pragma unroll
        for (int f = 0; f < FPB; f++) {
            int frame = fbase + f;
            if (frame < NFRAMES)
                g_mel[((size_t)b * NFRAMES + frame) * NMELS + m] = acc[f];
        }
    }
}

// ---------------- PCEN stage 1: per-chunk partial EMA (c = 0..30) -------
__global__ __launch_bounds__(128)
void pcen_part1_kernel() {
    const int m = threadIdx.x;
    const int b = blockIdx.x;
    const int c = blockIdx.y;          // 0..KCH-2 (all full chunks)

    const float* p = g_mel + ((size_t)b * NFRAMES + c * LCH) * NMELS + m;

    float state;
    if (c == 0) {
        state = p[0];
        #pragma unroll
        for (int t = 1; t < LCH; t++) {
            float v = p[(size_t)t * NMELS];
            state = fmaf(EMA_A, state, EMA_S * v);
        }
    } else {
        state = 0.0f;
        #pragma unroll
        for (int t = 0; t < LCH; t++) {
            float v = p[(size_t)t * NMELS];
            state = fmaf(EMA_A, state, EMA_S * v);
        }
    }
    g_T[((size_t)b * KCH + c) * NMELS + m] = state;
}

// ---------------- PCEN stage 2: serial chunk prefix ---------------------
__global__ __launch_bounds__(128)
void pcen_combine_kernel() {
    const int m = threadIdx.x;
    const int b = blockIdx.x;

    float Tv[KCH];
    #pragma unroll
    for (int c = 0; c < KCH; c++)
        Tv[c] = g_T[((size_t)b * KCH + c) * NMELS + m];

    float A = 1.0f;
    #pragma unroll
    for (int i = 0; i < LCH; i++) A *= EMA_A;

    float S = 0.0f;
    #pragma unroll
    for (int c = 0; c < KCH; c++) {
        g_Sin[((size_t)b * KCH + c) * NMELS + m] = S;
        S = fmaf(A, S, Tv[c]);
    }
}

// ---------------- PCEN stage 3: outputs ----------------------------------
__device__ __forceinline__ float pcen_f(float v, float M) {
    float pw = exp2f(-0.98f * __log2f(M + 1e-6f));     // (M+eps)^-0.98
    float y  = fmaf(v, pw, 2.0f);
    return y * rsqrtf(y) - 1.41421356237309515f;       // sqrt(y) - sqrt(2)
}

__global__ __launch_bounds__(128)
void pcen_part2_kernel(float* __restrict__ out) {
    const int m = threadIdx.x;
    const int b = blockIdx.x;
    const int c = blockIdx.y;

    const int t0 = c * LCH;
    const float* p = g_mel + ((size_t)b * NFRAMES + t0) * NMELS + m;
    float*       o = out  + ((size_t)b * NFRAMES + t0) * NMELS + m;

    if (c == 0) {
        float v0 = p[0];
        float state = v0;
        o[0] = pcen_f(v0, state);
        #pragma unroll
        for (int t = 1; t < LCH; t++) {
            float v = p[(size_t)t * NMELS];
            state = fmaf(EMA_A, state, EMA_S * v);
            o[(size_t)t * NMELS] = pcen_f(v, state);
        }
    } else if (c < KCH - 1) {
        float state = g_Sin[((size_t)b * KCH + c) * NMELS + m];
        #pragma unroll
        for (int t = 0; t < LCH; t++) {
            float v = p[(size_t)t * NMELS];
            state = fmaf(EMA_A, state, EMA_S * v);
            o[(size_t)t * NMELS] = pcen_f(v, state);
        }
    } else {
        float state = g_Sin[((size_t)b * KCH + c) * NMELS + m];
        #pragma unroll
        for (int t = 0; t < NFRAMES - (KCH - 1) * LCH; t++) {   // 6 frames
            float v = p[(size_t)t * NMELS];
            state = fmaf(EMA_A, state, EMA_S * v);
            o[(size_t)t * NMELS] = pcen_f(v, state);
        }
    }
}

// ---------------- launch ----------------
extern "C" void kernel_launch(void* const* d_in, const int* in_sizes, int n_in,
                              void* d_out, int out_size) {
    const float* x  = (const float*)d_in[0];   // (32, 160000) f32
    const float* fb = (const float*)d_in[1];   // (513, 128)  f32
    float* out = (float*)d_out;                // (32, 626, 128) f32

    prep_tw_kernel<<<4, 256>>>();
    prep_fb_kernel<<<NMELS, 32>>>(fb);
    // fft_mel split in two: the 4th launch is the one ncu captures
    fft_mel_kernel<<<dim3(NFBLK_A, BATCH), 128>>>(x, 0);
    fft_mel_kernel<<<dim3(NFBLK_B, BATCH), 128>>>(x, NFBLK_A);
    pcen_part1_kernel<<<dim3(BATCH, KCH - 1), 128>>>();
    pcen_combine_kernel<<<BATCH, 128>>>();
    pcen_part2_kernel<<<dim3(BATCH, KCH), 128>>>(out);
}

// round 8
// speedup vs baseline: 1.0595x; 1.0374x over previous
#include <cuda_runtime.h>
#include <math.h>

#define N_FFT   1024
#define HOP     256
#define NBINS   513
#define NMELS   128
#define BATCH   32
#define SIGLEN  160000
#define PAD     512
#define NFRAMES 626
#define NPAIRS  313
#define NPAIR_A 157            // split for profiling
#define NPAIR_B 156
#define SUP     26

#define KCH     32             // EMA chunks per chain
#define LCH     20             // frames per chunk
#define EMA_A   0.975f
#define EMA_S   0.025f

#define PADI(i) ((i) + ((i) >> 2))   // smem anti-conflict padding (len 1280)

// ---------------- device scratch ----------------
__device__ float  g_mel[BATCH * NFRAMES * NMELS];
__device__ float  g_T  [BATCH * KCH * NMELS];
__device__ float  g_Sin[BATCH * KCH * NMELS];
__device__ float  g_fbT[SUP * NMELS];
__device__ int    g_start[NMELS];
__device__ float2 g_tw[N_FFT];                     // exp(-2*pi*i*k/1024)

// ---------------- prep A: twiddles ----------------
__global__ void prep_tw_kernel() {
    int k = blockIdx.x * 256 + threadIdx.x;        // grid 4 -> 0..1023
    float ang = -6.283185307179586f * (float)k / (float)N_FFT;
    float s, c;
    sincosf(ang, &s, &c);
    g_tw[k] = make_float2(c, s);
}

// ---------------- prep B: fb compaction, one warp per mel ---------------
__global__ void prep_fb_kernel(const float* __restrict__ fb) {
    const int m    = blockIdx.x;
    const int lane = threadIdx.x;

    int first = 0x7fffffff, last = -1;
    for (int f = lane; f < NBINS; f += 32) {
        float v = fb[f * NMELS + m];
        if (v != 0.0f) { first = min(first, f); last = max(last, f); }
    }
    first = __reduce_min_sync(0xffffffffu, first);
    last  = __reduce_max_sync(0xffffffffu, last);

    int st  = (last < 0) ? 0 : first;
    int len = (last < 0) ? 0 : (last - first + 1);
    if (len > SUP) len = SUP;

    if (lane == 0) g_start[m] = st;
    if (lane < SUP) {
        int j = lane;
        g_fbT[j * NMELS + m] = (j < len) ? fb[(st + j) * NMELS + m] : 0.0f;
    }
}

__device__ __forceinline__ int reflect_idx(int src) {
    if (src < 0) src = -src;
    if (src >= SIGLEN) src = 2 * SIGLEN - 2 - src;
    return src;
}

// base-4 digit reversal of a 10-bit index (5 base-4 digits)
__device__ __forceinline__ int rev4(int k) {
    int r = __brev(k) >> 22;                           // 10-bit bit reverse
    return ((r & 0x155) << 1) | ((r & 0x2AA) >> 1);    // swap bit pairs
}

// ---------------- fft + mel: in-place radix-4 DIF, padded smem ----------
// 256 threads, 1 packed complex FFT (= 2 real frames) per block.
__global__ __launch_bounds__(256)
void fft_mel_kernel(const float* __restrict__ x, int poff) {
    __shared__ float  re[1280];            // 1024 + pad
    __shared__ float  im[1280];
    __shared__ float2 tws[768];            // twiddles used by stages
    __shared__ float  specA[NBINS + SUP + 1];
    __shared__ float  specB[NBINS + SUP + 1];

    const int tid = threadIdx.x;
    const int b   = blockIdx.y;
    const int pr  = blockIdx.x + poff;
    const int tA  = 2 * pr;

    const float* xb = x + (size_t)b * SIGLEN;

    // twiddle table to smem
    tws[tid]       = g_tw[tid];
    tws[tid + 256] = g_tw[tid + 256];
    tws[tid + 512] = g_tw[tid + 512];

    // ---- load two frames packed (A -> re, B -> im), natural order ----
    const int baseA = tA * HOP - PAD;
    const int baseB = baseA + HOP;
    if (baseA >= 0 && baseB + N_FFT <= SIGLEN) {
        #pragma unroll
        for (int k = 0; k < 4; k++) {
            int n = tid + 256 * k;
            re[PADI(n)] = xb[baseA + n];
            im[PADI(n)] = xb[baseB + n];
        }
    } else {
        #pragma unroll
        for (int k = 0; k < 4; k++) {
            int n = tid + 256 * k;
            re[PADI(n)] = xb[reflect_idx(baseA + n)];
            im[PADI(n)] = xb[reflect_idx(baseB + n)];
        }
    }
    __syncthreads();

    // ---- 5 radix-4 DIF stages, strides 256,64,16,4,1 ----
    // Each thread owns one butterfly (4 disjoint slots) -> 1 barrier/stage.
    #pragma unroll
    for (int st = 0; st < 5; st++) {
        const int lg = 8 - 2 * st;             // log2(S)
        const int S  = 1 << lg;
        const int r  = tid & (S - 1);
        const int o  = ((tid >> lg) << (lg + 2)) + r;
        const int i0 = PADI(o);
        const int i1 = PADI(o + S);
        const int i2 = PADI(o + 2 * S);
        const int i3 = PADI(o + 3 * S);

        float ar = re[i0], ai = im[i0];
        float br = re[i1], bi = im[i1];
        float cr = re[i2], ci = im[i2];
        float dr = re[i3], di = im[i3];

        float t0r = ar + cr, t0i = ai + ci;
        float t1r = ar - cr, t1i = ai - ci;
        float t2r = br + dr, t2i = bi + di;
        float t3r = br - dr, t3i = bi - di;

        re[i0] = t0r + t2r;  im[i0] = t0i + t2i;          // y0
        float y1r = t1r + t3i, y1i = t1i - t3r;           // t1 - i*t3
        float y2r = t0r - t2r, y2i = t0i - t2i;
        float y3r = t1r - t3i, y3i = t1i + t3r;           // t1 + i*t3

        if (st < 4) {
            const int tf = 1 << (2 * st);                 // 1024 / (4S)
            float2 w1 = tws[r * tf];
            float2 w2 = tws[2 * r * tf];
            float2 w3 = tws[3 * r * tf];
            re[i1] = y1r * w1.x - y1i * w1.y;  im[i1] = y1r * w1.y + y1i * w1.x;
            re[i2] = y2r * w2.x - y2i * w2.y;  im[i2] = y2r * w2.y + y2i * w2.x;
            re[i3] = y3r * w3.x - y3i * w3.y;  im[i3] = y3r * w3.y + y3i * w3.x;
        } else {
            re[i1] = y1r;  im[i1] = y1i;
            re[i2] = y2r;  im[i2] = y2i;
            re[i3] = y3r;  im[i3] = y3i;
        }
        __syncthreads();
    }
    // X[k] now lives at padded position rev4(k)

    // ---- conjugate unpack + magnitude into natural-order spec ----
    #pragma unroll
    for (int k = tid; k < NBINS; k += 256) {
        int nk = (N_FFT - k) & (N_FFT - 1);
        int p1 = PADI(rev4(k));
        int p2 = PADI(rev4(nk));
        float rk = re[p1], ik = im[p1];
        float rn = re[p2], in_ = im[p2];
        float ar = 0.5f * (rk + rn);
        float ai = 0.5f * (ik - in_);
        float brr = 0.5f * (ik + in_);
        float bii = 0.5f * (rn - rk);
        specA[k] = sqrtf(ar * ar + ai * ai);
        specB[k] = sqrtf(brr * brr + bii * bii);
    }
    for (int k = NBINS + tid; k < NBINS + SUP; k += 256) {
        specA[k] = 0.0f;  specB[k] = 0.0f;
    }
    __syncthreads();

    // ---- sparse mel: tid<128 -> frame A, tid>=128 -> frame B ----
    {
        const int m  = tid & (NMELS - 1);
        const float* spec = (tid < NMELS) ? specA : specB;
        const int st = g_start[m];
        float acc = 0.0f;
        #pragma unroll
        for (int j = 0; j < SUP; j++)
            acc += spec[st + j] * g_fbT[j * NMELS + m];
        int frame = tA + (tid >> 7);
        g_mel[((size_t)b * NFRAMES + frame) * NMELS + m] = acc;
    }
}

// ---------------- PCEN stage 1: per-chunk partial EMA (c = 0..30) -------
__global__ __launch_bounds__(128)
void pcen_part1_kernel() {
    const int m = threadIdx.x;
    const int b = blockIdx.x;
    const int c = blockIdx.y;

    const float* p = g_mel + ((size_t)b * NFRAMES + c * LCH) * NMELS + m;

    float state;
    if (c == 0) {
        state = p[0];
        #pragma unroll
        for (int t = 1; t < LCH; t++) {
            float v = p[(size_t)t * NMELS];
            state = fmaf(EMA_A, state, EMA_S * v);
        }
    } else {
        state = 0.0f;
        #pragma unroll
        for (int t = 0; t < LCH; t++) {
            float v = p[(size_t)t * NMELS];
            state = fmaf(EMA_A, state, EMA_S * v);
        }
    }
    g_T[((size_t)b * KCH + c) * NMELS + m] = state;
}

// ---------------- PCEN stage 2: serial chunk prefix ---------------------
__global__ __launch_bounds__(128)
void pcen_combine_kernel() {
    const int m = threadIdx.x;
    const int b = blockIdx.x;

    float Tv[KCH];
    #pragma unroll
    for (int c = 0; c < KCH; c++)
        Tv[c] = g_T[((size_t)b * KCH + c) * NMELS + m];

    float A = 1.0f;
    #pragma unroll
    for (int i = 0; i < LCH; i++) A *= EMA_A;

    float S = 0.0f;
    #pragma unroll
    for (int c = 0; c < KCH; c++) {
        g_Sin[((size_t)b * KCH + c) * NMELS + m] = S;
        S = fmaf(A, S, Tv[c]);
    }
}

// ---------------- PCEN stage 3: outputs ----------------------------------
__device__ __forceinline__ float pcen_f(float v, float M) {
    float pw = exp2f(-0.98f * __log2f(M + 1e-6f));     // (M+eps)^-0.98
    float y  = fmaf(v, pw, 2.0f);
    return y * rsqrtf(y) - 1.41421356237309515f;       // sqrt(y) - sqrt(2)
}

__global__ __launch_bounds__(128)
void pcen_part2_kernel(float* __restrict__ out) {
    const int m = threadIdx.x;
    const int b = blockIdx.x;
    const int c = blockIdx.y;

    const int t0 = c * LCH;
    const float* p = g_mel + ((size_t)b * NFRAMES + t0) * NMELS + m;
    float*       o = out  + ((size_t)b * NFRAMES + t0) * NMELS + m;

    if (c == 0) {
        float v0 = p[0];
        float state = v0;
        o[0] = pcen_f(v0, state);
        #pragma unroll
        for (int t = 1; t < LCH; t++) {
            float v = p[(size_t)t * NMELS];
            state = fmaf(EMA_A, state, EMA_S * v);
            o[(size_t)t * NMELS] = pcen_f(v, state);
        }
    } else if (c < KCH - 1) {
        float state = g_Sin[((size_t)b * KCH + c) * NMELS + m];
        #pragma unroll
        for (int t = 0; t < LCH; t++) {
            float v = p[(size_t)t * NMELS];
            state = fmaf(EMA_A, state, EMA_S * v);
            o[(size_t)t * NMELS] = pcen_f(v, state);
        }
    } else {
        float state = g_Sin[((size_t)b * KCH + c) * NMELS + m];
        #pragma unroll
        for (int t = 0; t < NFRAMES - (KCH - 1) * LCH; t++) {   // 6 frames
            float v = p[(size_t)t * NMELS];
            state = fmaf(EMA_A, state, EMA_S * v);
            o[(size_t)t * NMELS] = pcen_f(v, state);
        }
    }
}

// ---------------- launch ----------------
extern "C" void kernel_launch(void* const* d_in, const int* in_sizes, int n_in,
                              void* d_out, int out_size) {
    const float* x  = (const float*)d_in[0];   // (32, 160000) f32
    const float* fb = (const float*)d_in[1];   // (513, 128)  f32
    float* out = (float*)d_out;                // (32, 626, 128) f32

    prep_tw_kernel<<<4, 256>>>();
    prep_fb_kernel<<<NMELS, 32>>>(fb);
    // fft split in two launches so ncu (position 4) lands on fft_mel
    fft_mel_kernel<<<dim3(NPAIR_A, BATCH), 256>>>(x, 0);
    fft_mel_kernel<<<dim3(NPAIR_B, BATCH), 256>>>(x, NPAIR_A);
    pcen_part1_kernel<<<dim3(BATCH, KCH - 1), 128>>>();
    pcen_combine_kernel<<<BATCH, 128>>>();
    pcen_part2_kernel<<<dim3(BATCH, KCH), 128>>>(out);
}

// round 9
// speedup vs baseline: 1.7593x; 1.6604x over previous
#include <cuda_runtime.h>
#include <math.h>

#define N_FFT   1024
#define HOP     256
#define NBINS   513
#define NMELS   128
#define BATCH   32
#define SIGLEN  160000
#define PAD     512
#define NFRAMES 626
#define NPAIRS  313
#define NBLK    79             // ceil(313/4) blocks per batch row
#define NBLK_A  40             // split for profiling (ncu lands on pos 4)
#define NBLK_B  39
#define SUP     26

#define KCH     32
#define LCH     20
#define EMA_A   0.975f
#define EMA_S   0.025f

#define PADI(i) ((i) + ((i) >> 4))   // anti-conflict padding
#define FSZ     1088                 // PADI(1023)=1086, rounded up

// ---------------- device scratch ----------------
__device__ float  g_mel[BATCH * NFRAMES * NMELS];
__device__ float  g_T  [BATCH * KCH * NMELS];
__device__ float  g_Sin[BATCH * KCH * NMELS];
__device__ float  g_fbT[SUP * NMELS];
__device__ int    g_start[NMELS];
__device__ float2 g_tw[N_FFT];

// ---------------- prep A: twiddles ----------------
__global__ void prep_tw_kernel() {
    int k = blockIdx.x * 256 + threadIdx.x;
    float ang = -6.283185307179586f * (float)k / (float)N_FFT;
    float s, c;
    sincosf(ang, &s, &c);
    g_tw[k] = make_float2(c, s);
}

// ---------------- prep B: fb compaction ----------------
__global__ void prep_fb_kernel(const float* __restrict__ fb) {
    const int m    = blockIdx.x;
    const int lane = threadIdx.x;

    int first = 0x7fffffff, last = -1;
    for (int f = lane; f < NBINS; f += 32) {
        float v = fb[f * NMELS + m];
        if (v != 0.0f) { first = min(first, f); last = max(last, f); }
    }
    first = __reduce_min_sync(0xffffffffu, first);
    last  = __reduce_max_sync(0xffffffffu, last);

    int st  = (last < 0) ? 0 : first;
    int len = (last < 0) ? 0 : (last - first + 1);
    if (len > SUP) len = SUP;

    if (lane == 0) g_start[m] = st;
    if (lane < SUP) {
        int j = lane;
        g_fbT[j * NMELS + m] = (j < len) ? fb[(st + j) * NMELS + m] : 0.0f;
    }
}

__device__ __forceinline__ int reflect_idx(int src) {
    if (src < 0) src = -src;
    if (src >= SIGLEN) src = 2 * SIGLEN - 2 - src;
    return src;
}

// base-4 digit reversal of 10-bit index
__device__ __forceinline__ int rev4(int k) {
    int r = __brev(k) >> 22;
    return ((r & 0x155) << 1) | ((r & 0x2AA) >> 1);
}

// radix-4 DIF butterfly core: in/out through y registers
#define R4BFLY(x0r,x0i,x1r,x1i,x2r,x2i,x3r,x3i,                          \
               y0r,y0i,y1r,y1i,y2r,y2i,y3r,y3i)                          \
    {                                                                     \
        float t0r = (x0r)+(x2r), t0i = (x0i)+(x2i);                       \
        float t1r = (x0r)-(x2r), t1i = (x0i)-(x2i);                       \
        float t2r = (x1r)+(x3r), t2i = (x1i)+(x3i);                       \
        float t3r = (x1r)-(x3r), t3i = (x1i)-(x3i);                       \
        y0r = t0r + t2r;  y0i = t0i + t2i;                                \
        y1r = t1r + t3i;  y1i = t1i - t3r;                                \
        y2r = t0r - t2r;  y2i = t0i - t2i;                                \
        y3r = t1r - t3i;  y3i = t1i + t3r;                                \
    }

// ---------------- fft + mel: 3-pass fused radix-4, 4 FFTs/block ---------
// 256 threads = 4 FFTs x 64 threads; each FFT packs 2 real frames.
__global__ __launch_bounds__(256, 2)
void fft_mel_kernel(const float* __restrict__ x, int blkoff) {
    __shared__ float  re[4 * FSZ];       // 17.4 KB
    __shared__ float  im[4 * FSZ];       // 17.4 KB
    __shared__ float2 tws[768];          // 6 KB

    const int tid = threadIdx.x;
    const int q   = tid >> 6;            // FFT unit 0..3
    const int t   = tid & 63;            // thread within FFT
    const int b   = blockIdx.y;
    const int p0  = (blockIdx.x + blkoff) * 4 + q;   // logical pair index
    const int pr  = min(p0, NPAIRS - 1);             // clamped for loads

    const float* xb = x + (size_t)b * SIGLEN;
    float* mre = re + q * FSZ;
    float* mim = im + q * FSZ;

    // stage twiddles
    tws[tid]       = g_tw[tid];
    tws[tid + 256] = g_tw[tid + 256];
    tws[tid + 512] = g_tw[tid + 512];

    // ---- load frames (2pr, 2pr+1) packed: A->re, B->im ----
    const int baseA = 2 * pr * HOP - PAD;
    const int baseB = baseA + HOP;
    if (baseA >= 0 && baseB + N_FFT <= SIGLEN) {
        #pragma unroll
        for (int k = 0; k < 16; k++) {
            int n = t + 64 * k;
            mre[PADI(n)] = xb[baseA + n];
            mim[PADI(n)] = xb[baseB + n];
        }
    } else {
        #pragma unroll 4
        for (int k = 0; k < 16; k++) {
            int n = t + 64 * k;
            mre[PADI(n)] = xb[reflect_idx(baseA + n)];
            mim[PADI(n)] = xb[reflect_idx(baseB + n)];
        }
    }
    __syncthreads();

    float xr[4][4], xi[4][4];

    // ================= PASS A: stages S=256 (over a), S=64 (over b) =====
    #pragma unroll
    for (int a = 0; a < 4; a++)
        #pragma unroll
        for (int bb = 0; bb < 4; bb++) {
            int p = PADI(t + 64 * bb + 256 * a);
            xr[a][bb] = mre[p];  xi[a][bb] = mim[p];
        }
    // stage 0: butterfly over a; twiddle r = t + 64b, tf=1
    #pragma unroll
    for (int bb = 0; bb < 4; bb++) {
        float y0r,y0i,y1r,y1i,y2r,y2i,y3r,y3i;
        R4BFLY(xr[0][bb],xi[0][bb], xr[1][bb],xi[1][bb],
               xr[2][bb],xi[2][bb], xr[3][bb],xi[3][bb],
               y0r,y0i,y1r,y1i,y2r,y2i,y3r,y3i);
        int r = t + 64 * bb;
        float2 w1 = tws[r], w2 = tws[2 * r], w3 = tws[3 * r];
        xr[0][bb] = y0r;                      xi[0][bb] = y0i;
        xr[1][bb] = y1r*w1.x - y1i*w1.y;      xi[1][bb] = y1r*w1.y + y1i*w1.x;
        xr[2][bb] = y2r*w2.x - y2i*w2.y;      xi[2][bb] = y2r*w2.y + y2i*w2.x;
        xr[3][bb] = y3r*w3.x - y3i*w3.y;      xi[3][bb] = y3r*w3.y + y3i*w3.x;
    }
    // stage 1: butterfly over b; twiddle r = t, tf=4
    {
        float2 w1 = tws[4 * t], w2 = tws[8 * t], w3 = tws[12 * t];
        #pragma unroll
        for (int a = 0; a < 4; a++) {
            float y0r,y0i,y1r,y1i,y2r,y2i,y3r,y3i;
            R4BFLY(xr[a][0],xi[a][0], xr[a][1],xi[a][1],
                   xr[a][2],xi[a][2], xr[a][3],xi[a][3],
                   y0r,y0i,y1r,y1i,y2r,y2i,y3r,y3i);
            xr[a][0] = y0r;                   xi[a][0] = y0i;
            xr[a][1] = y1r*w1.x - y1i*w1.y;   xi[a][1] = y1r*w1.y + y1i*w1.x;
            xr[a][2] = y2r*w2.x - y2i*w2.y;   xi[a][2] = y2r*w2.y + y2i*w2.x;
            xr[a][3] = y3r*w3.x - y3i*w3.y;   xi[a][3] = y3r*w3.y + y3i*w3.x;
        }
    }
    #pragma unroll
    for (int a = 0; a < 4; a++)
        #pragma unroll
        for (int bb = 0; bb < 4; bb++) {
            int p = PADI(t + 64 * bb + 256 * a);
            mre[p] = xr[a][bb];  mim[p] = xi[a][bb];
        }
    __syncthreads();

    // ================= PASS B: stages S=16 (over c), S=4 (over d) =======
    {
        const int d4 = t >> 4, d3 = (t >> 2) & 3, d0 = t & 3;
        const int base = 256 * d4 + 64 * d3 + d0;
        #pragma unroll
        for (int c = 0; c < 4; c++)
            #pragma unroll
            for (int d = 0; d < 4; d++) {
                int p = PADI(base + 16 * c + 4 * d);
                xr[c][d] = mre[p];  xi[c][d] = mim[p];
            }
        // stage 2: butterfly over c; twiddle r = d0 + 4d, tf=16
        #pragma unroll
        for (int d = 0; d < 4; d++) {
            float y0r,y0i,y1r,y1i,y2r,y2i,y3r,y3i;
            R4BFLY(xr[0][d],xi[0][d], xr[1][d],xi[1][d],
                   xr[2][d],xi[2][d], xr[3][d],xi[3][d],
                   y0r,y0i,y1r,y1i,y2r,y2i,y3r,y3i);
            int r = (d0 + 4 * d) * 16;
            float2 w1 = tws[r], w2 = tws[2 * r], w3 = tws[3 * r];
            xr[0][d] = y0r;                   xi[0][d] = y0i;
            xr[1][d] = y1r*w1.x - y1i*w1.y;   xi[1][d] = y1r*w1.y + y1i*w1.x;
            xr[2][d] = y2r*w2.x - y2i*w2.y;   xi[2][d] = y2r*w2.y + y2i*w2.x;
            xr[3][d] = y3r*w3.x - y3i*w3.y;   xi[3][d] = y3r*w3.y + y3i*w3.x;
        }
        // stage 3: butterfly over d; twiddle r = d0, tf=64
        {
            float2 w1 = tws[64 * d0], w2 = tws[128 * d0], w3 = tws[192 * d0];
            #pragma unroll
            for (int c = 0; c < 4; c++) {
                float y0r,y0i,y1r,y1i,y2r,y2i,y3r,y3i;
                R4BFLY(xr[c][0],xi[c][0], xr[c][1],xi[c][1],
                       xr[c][2],xi[c][2], xr[c][3],xi[c][3],
                       y0r,y0i,y1r,y1i,y2r,y2i,y3r,y3i);
                xr[c][0] = y0r;                   xi[c][0] = y0i;
                xr[c][1] = y1r*w1.x - y1i*w1.y;   xi[c][1] = y1r*w1.y + y1i*w1.x;
                xr[c][2] = y2r*w2.x - y2i*w2.y;   xi[c][2] = y2r*w2.y + y2i*w2.x;
                xr[c][3] = y3r*w3.x - y3i*w3.y;   xi[c][3] = y3r*w3.y + y3i*w3.x;
            }
        }
        #pragma unroll
        for (int c = 0; c < 4; c++)
            #pragma unroll
            for (int d = 0; d < 4; d++) {
                int p = PADI(base + 16 * c + 4 * d);
                mre[p] = xr[c][d];  mim[p] = xi[c][d];
            }
    }
    __syncthreads();

    // ================= PASS C: stage S=1 (no twiddle) ====================
    #pragma unroll
    for (int g = 0; g < 4; g++) {
        int o = 16 * t + 4 * g;
        int p0i = PADI(o), p1i = PADI(o + 1), p2i = PADI(o + 2), p3i = PADI(o + 3);
        float x0r = mre[p0i], x0i = mim[p0i];
        float x1r = mre[p1i], x1i = mim[p1i];
        float x2r = mre[p2i], x2i = mim[p2i];
        float x3r = mre[p3i], x3i = mim[p3i];
        float y0r,y0i,y1r,y1i,y2r,y2i,y3r,y3i;
        R4BFLY(x0r,x0i, x1r,x1i, x2r,x2i, x3r,x3i,
               y0r,y0i,y1r,y1i,y2r,y2i,y3r,y3i);
        mre[p0i] = y0r;  mim[p0i] = y0i;
        mre[p1i] = y1r;  mim[p1i] = y1i;
        mre[p2i] = y2r;  mim[p2i] = y2i;
        mre[p3i] = y3r;  mim[p3i] = y3i;
    }
    __syncthreads();
    // X[k] lives at padded position rev4(k)

    // ---- unpack to registers (reads), then overlay spec on re/im ------
    float magA[9], magB[9];
    #pragma unroll
    for (int i = 0; i < 9; i++) {
        int k = t + 64 * i;
        if (k < NBINS) {
            int nk = (N_FFT - k) & (N_FFT - 1);
            int p1 = PADI(rev4(k));
            int p2 = PADI(rev4(nk));
            float rk = mre[p1], ik = mim[p1];
            float rn = mre[p2], in_ = mim[p2];
            float ar = 0.5f * (rk + rn);
            float ai = 0.5f * (ik - in_);
            float br = 0.5f * (ik + in_);
            float bi = 0.5f * (rn - rk);
            magA[i] = sqrtf(ar * ar + ai * ai);
            magB[i] = sqrtf(br * br + bi * bi);
        }
    }
    __syncthreads();   // all reads done before spec overlays re/im

    #pragma unroll
    for (int i = 0; i < 9; i++) {
        int k = t + 64 * i;
        if (k < NBINS) { mre[k] = magA[i]; mim[k] = magB[i]; }
    }
    if (t < SUP) { mre[NBINS + t] = 0.0f; mim[NBINS + t] = 0.0f; }
    __syncthreads();

    // ---- sparse mel: thread = (mel m, frame-half fh), all 4 FFTs -------
    {
        const int m  = tid & (NMELS - 1);
        const int fh = tid >> 7;                 // 0: frame A, 1: frame B
        const int st = g_start[m];
        const float* base = (fh ? im : re);
        float acc[4];
        #pragma unroll
        for (int qq = 0; qq < 4; qq++) acc[qq] = 0.0f;
        #pragma unroll
        for (int j = 0; j < SUP; j++) {
            float fv = g_fbT[j * NMELS + m];
            #pragma unroll
            for (int qq = 0; qq < 4; qq++)
                acc[qq] += base[qq * FSZ + st + j] * fv;
        }
        const int pbase = (blockIdx.x + blkoff) * 4;
        #pragma unroll
        for (int qq = 0; qq < 4; qq++) {
            int frame = 2 * (pbase + qq) + fh;
            if (frame < NFRAMES)
                g_mel[((size_t)b * NFRAMES + frame) * NMELS + m] = acc[qq];
        }
    }
}

// ---------------- PCEN stage 1 ----------------
__global__ __launch_bounds__(128)
void pcen_part1_kernel() {
    const int m = threadIdx.x;
    const int b = blockIdx.x;
    const int c = blockIdx.y;

    const float* p = g_mel + ((size_t)b * NFRAMES + c * LCH) * NMELS + m;

    float state;
    if (c == 0) {
        state = p[0];
        #pragma unroll
        for (int t = 1; t < LCH; t++) {
            float v = p[(size_t)t * NMELS];
            state = fmaf(EMA_A, state, EMA_S * v);
        }
    } else {
        state = 0.0f;
        #pragma unroll
        for (int t = 0; t < LCH; t++) {
            float v = p[(size_t)t * NMELS];
            state = fmaf(EMA_A, state, EMA_S * v);
        }
    }
    g_T[((size_t)b * KCH + c) * NMELS + m] = state;
}

// ---------------- PCEN stage 2 ----------------
__global__ __launch_bounds__(128)
void pcen_combine_kernel() {
    const int m = threadIdx.x;
    const int b = blockIdx.x;

    float Tv[KCH];
    #pragma unroll
    for (int c = 0; c < KCH; c++)
        Tv[c] = g_T[((size_t)b * KCH + c) * NMELS + m];

    float A = 1.0f;
    #pragma unroll
    for (int i = 0; i < LCH; i++) A *= EMA_A;

    float S = 0.0f;
    #pragma unroll
    for (int c = 0; c < KCH; c++) {
        g_Sin[((size_t)b * KCH + c) * NMELS + m] = S;
        S = fmaf(A, S, Tv[c]);
    }
}

// ---------------- PCEN stage 3 ----------------
__device__ __forceinline__ float pcen_f(float v, float M) {
    float pw = exp2f(-0.98f * __log2f(M + 1e-6f));
    float y  = fmaf(v, pw, 2.0f);
    return y * rsqrtf(y) - 1.41421356237309515f;
}

__global__ __launch_bounds__(128)
void pcen_part2_kernel(float* __restrict__ out) {
    const int m = threadIdx.x;
    const int b = blockIdx.x;
    const int c = blockIdx.y;

    const int t0 = c * LCH;
    const float* p = g_mel + ((size_t)b * NFRAMES + t0) * NMELS + m;
    float*       o = out  + ((size_t)b * NFRAMES + t0) * NMELS + m;

    if (c == 0) {
        float v0 = p[0];
        float state = v0;
        o[0] = pcen_f(v0, state);
        #pragma unroll
        for (int t = 1; t < LCH; t++) {
            float v = p[(size_t)t * NMELS];
            state = fmaf(EMA_A, state, EMA_S * v);
            o[(size_t)t * NMELS] = pcen_f(v, state);
        }
    } else if (c < KCH - 1) {
        float state = g_Sin[((size_t)b * KCH + c) * NMELS + m];
        #pragma unroll
        for (int t = 0; t < LCH; t++) {
            float v = p[(size_t)t * NMELS];
            state = fmaf(EMA_A, state, EMA_S * v);
            o[(size_t)t * NMELS] = pcen_f(v, state);
        }
    } else {
        float state = g_Sin[((size_t)b * KCH + c) * NMELS + m];
        #pragma unroll
        for (int t = 0; t < NFRAMES - (KCH - 1) * LCH; t++) {
            float v = p[(size_t)t * NMELS];
            state = fmaf(EMA_A, state, EMA_S * v);
            o[(size_t)t * NMELS] = pcen_f(v, state);
        }
    }
}

// ---------------- launch ----------------
extern "C" void kernel_launch(void* const* d_in, const int* in_sizes, int n_in,
                              void* d_out, int out_size) {
    const float* x  = (const float*)d_in[0];   // (32, 160000) f32
    const float* fb = (const float*)d_in[1];   // (513, 128)  f32
    float* out = (float*)d_out;                // (32, 626, 128) f32

    prep_tw_kernel<<<4, 256>>>();
    prep_fb_kernel<<<NMELS, 32>>>(fb);
    fft_mel_kernel<<<dim3(NBLK_A, BATCH), 256>>>(x, 0);
    fft_mel_kernel<<<dim3(NBLK_B, BATCH), 256>>>(x, NBLK_A);
    pcen_part1_kernel<<<dim3(BATCH, KCH - 1), 128>>>();
    pcen_combine_kernel<<<BATCH, 128>>>();
    pcen_part2_kernel<<<dim3(BATCH, KCH), 128>>>(out);
}

// round 10
// speedup vs baseline: 1.9446x; 1.1053x over previous
#include <cuda_runtime.h>
#include <math.h>

#define N_FFT   1024
#define HOP     256
#define NBINS   513
#define NMELS   128
#define BATCH   32
#define SIGLEN  160000
#define PAD     512
#define NFRAMES 626
#define NPAIRS  313
#define NBLK_A  40             // split for profiling (ncu lands on launch #4)
#define NBLK_B  39
#define SUP     26

#define KCH     32
#define LCH     20
#define EMA_A   0.975f
#define EMA_S   0.025f

#define PADI(i) ((i) + ((i) >> 4))   // anti-conflict padding
#define FSZ     1088                 // floats per FFT unit (544 float2)

// ---------------- device scratch ----------------
__device__ float  g_mel[BATCH * NFRAMES * NMELS];
__device__ float  g_T  [BATCH * KCH * NMELS];
__device__ float  g_fbT[SUP * NMELS];
__device__ int    g_start[NMELS];
__device__ float2 g_tw[N_FFT];

// ---------------- prep A: twiddles ----------------
__global__ void prep_tw_kernel() {
    int k = blockIdx.x * 256 + threadIdx.x;
    float ang = -6.283185307179586f * (float)k / (float)N_FFT;
    float s, c;
    sincosf(ang, &s, &c);
    g_tw[k] = make_float2(c, s);
}

// ---------------- prep B: fb compaction ----------------
__global__ void prep_fb_kernel(const float* __restrict__ fb) {
    const int m    = blockIdx.x;
    const int lane = threadIdx.x;

    int first = 0x7fffffff, last = -1;
    for (int f = lane; f < NBINS; f += 32) {
        float v = fb[f * NMELS + m];
        if (v != 0.0f) { first = min(first, f); last = max(last, f); }
    }
    first = __reduce_min_sync(0xffffffffu, first);
    last  = __reduce_max_sync(0xffffffffu, last);

    int st  = (last < 0) ? 0 : first;
    int len = (last < 0) ? 0 : (last - first + 1);
    if (len > SUP) len = SUP;

    if (lane == 0) g_start[m] = st;
    if (lane < SUP) {
        int j = lane;
        g_fbT[j * NMELS + m] = (j < len) ? fb[(st + j) * NMELS + m] : 0.0f;
    }
}

__device__ __forceinline__ int reflect_idx(int src) {
    if (src < 0) src = -src;
    if (src >= SIGLEN) src = 2 * SIGLEN - 2 - src;
    return src;
}

// base-4 digit reversal of 10-bit index
__device__ __forceinline__ int rev4(int k) {
    int r = __brev(k) >> 22;
    return ((r & 0x155) << 1) | ((r & 0x2AA) >> 1);
}

#define R4BFLY(x0r,x0i,x1r,x1i,x2r,x2i,x3r,x3i,                          \
               y0r,y0i,y1r,y1i,y2r,y2i,y3r,y3i)                          \
    {                                                                     \
        float t0r = (x0r)+(x2r), t0i = (x0i)+(x2i);                       \
        float t1r = (x0r)-(x2r), t1i = (x0i)-(x2i);                       \
        float t2r = (x1r)+(x3r), t2i = (x1i)+(x3i);                       \
        float t3r = (x1r)-(x3r), t3i = (x1i)-(x3i);                       \
        y0r = t0r + t2r;  y0i = t0i + t2i;                                \
        y1r = t1r + t3i;  y1i = t1i - t3r;                                \
        y2r = t0r - t2r;  y2i = t0i - t2i;                                \
        y3r = t1r - t3i;  y3i = t1i + t3r;                                \
    }

// ---------------- fft + mel: gmem->reg pass A, 3 smem phases ------------
// 256 threads = 4 FFTs x 64 threads; each FFT packs 2 real frames.
__global__ __launch_bounds__(256, 2)
void fft_mel_kernel(const float* __restrict__ x, int blkoff) {
    __shared__ float  re[4 * FSZ];       // 17.4 KB (FFT data, later spec f2)
    __shared__ float  im[4 * FSZ];       // 17.4 KB
    __shared__ float2 tws[768];          // 6 KB

    const int tid = threadIdx.x;
    const int q   = tid >> 6;            // FFT unit 0..3
    const int t   = tid & 63;            // thread within FFT
    const int b   = blockIdx.y;
    const int p0  = (blockIdx.x + blkoff) * 4 + q;
    const int pr  = min(p0, NPAIRS - 1);

    const float* xb = x + (size_t)b * SIGLEN;
    float* mre = re + q * FSZ;
    float* mim = im + q * FSZ;

    tws[tid]       = g_tw[tid];
    tws[tid + 256] = g_tw[tid + 256];
    tws[tid + 512] = g_tw[tid + 512];

    // ---- pass A source: straight from gmem into registers --------------
    const int baseA = 2 * pr * HOP - PAD;
    const int baseB = baseA + HOP;
    float xr[4][4], xi[4][4];
    if (pr >= 1 && pr <= 310) {          // fully interior
        #pragma unroll
        for (int a = 0; a < 4; a++)
            #pragma unroll
            for (int bb = 0; bb < 4; bb++) {
                int n = t + 64 * bb + 256 * a;
                xr[a][bb] = xb[baseA + n];
                xi[a][bb] = xb[baseB + n];
            }
    } else {
        #pragma unroll
        for (int a = 0; a < 4; a++)
            #pragma unroll
            for (int bb = 0; bb < 4; bb++) {
                int n = t + 64 * bb + 256 * a;
                xr[a][bb] = xb[reflect_idx(baseA + n)];
                xi[a][bb] = xb[reflect_idx(baseB + n)];
            }
    }
    __syncthreads();   // tws visible (LDGs complete via scoreboard later)

    // ================= PASS A: stages S=256 (a), S=64 (b) ===============
    #pragma unroll
    for (int bb = 0; bb < 4; bb++) {
        float y0r,y0i,y1r,y1i,y2r,y2i,y3r,y3i;
        R4BFLY(xr[0][bb],xi[0][bb], xr[1][bb],xi[1][bb],
               xr[2][bb],xi[2][bb], xr[3][bb],xi[3][bb],
               y0r,y0i,y1r,y1i,y2r,y2i,y3r,y3i);
        int r = t + 64 * bb;
        float2 w1 = tws[r], w2 = tws[2 * r], w3 = tws[3 * r];
        xr[0][bb] = y0r;                      xi[0][bb] = y0i;
        xr[1][bb] = y1r*w1.x - y1i*w1.y;      xi[1][bb] = y1r*w1.y + y1i*w1.x;
        xr[2][bb] = y2r*w2.x - y2i*w2.y;      xi[2][bb] = y2r*w2.y + y2i*w2.x;
        xr[3][bb] = y3r*w3.x - y3i*w3.y;      xi[3][bb] = y3r*w3.y + y3i*w3.x;
    }
    {
        float2 w1 = tws[4 * t], w2 = tws[8 * t], w3 = tws[12 * t];
        #pragma unroll
        for (int a = 0; a < 4; a++) {
            float y0r,y0i,y1r,y1i,y2r,y2i,y3r,y3i;
            R4BFLY(xr[a][0],xi[a][0], xr[a][1],xi[a][1],
                   xr[a][2],xi[a][2], xr[a][3],xi[a][3],
                   y0r,y0i,y1r,y1i,y2r,y2i,y3r,y3i);
            xr[a][0] = y0r;                   xi[a][0] = y0i;
            xr[a][1] = y1r*w1.x - y1i*w1.y;   xi[a][1] = y1r*w1.y + y1i*w1.x;
            xr[a][2] = y2r*w2.x - y2i*w2.y;   xi[a][2] = y2r*w2.y + y2i*w2.x;
            xr[a][3] = y3r*w3.x - y3i*w3.y;   xi[a][3] = y3r*w3.y + y3i*w3.x;
        }
    }
    #pragma unroll
    for (int a = 0; a < 4; a++)
        #pragma unroll
        for (int bb = 0; bb < 4; bb++) {
            int p = PADI(t + 64 * bb + 256 * a);
            mre[p] = xr[a][bb];  mim[p] = xi[a][bb];
        }
    __syncthreads();

    // ================= PASS B: stages S=16 (c), S=4 (d) =================
    {
        const int d4 = t >> 4, d3 = (t >> 2) & 3, d0 = t & 3;
        const int base = 256 * d4 + 64 * d3 + d0;
        #pragma unroll
        for (int c = 0; c < 4; c++)
            #pragma unroll
            for (int d = 0; d < 4; d++) {
                int p = PADI(base + 16 * c + 4 * d);
                xr[c][d] = mre[p];  xi[c][d] = mim[p];
            }
        #pragma unroll
        for (int d = 0; d < 4; d++) {
            float y0r,y0i,y1r,y1i,y2r,y2i,y3r,y3i;
            R4BFLY(xr[0][d],xi[0][d], xr[1][d],xi[1][d],
                   xr[2][d],xi[2][d], xr[3][d],xi[3][d],
                   y0r,y0i,y1r,y1i,y2r,y2i,y3r,y3i);
            int r = (d0 + 4 * d) * 16;
            float2 w1 = tws[r], w2 = tws[2 * r], w3 = tws[3 * r];
            xr[0][d] = y0r;                   xi[0][d] = y0i;
            xr[1][d] = y1r*w1.x - y1i*w1.y;   xi[1][d] = y1r*w1.y + y1i*w1.x;
            xr[2][d] = y2r*w2.x - y2i*w2.y;   xi[2][d] = y2r*w2.y + y2i*w2.x;
            xr[3][d] = y3r*w3.x - y3i*w3.y;   xi[3][d] = y3r*w3.y + y3i*w3.x;
        }
        {
            float2 w1 = tws[64 * d0], w2 = tws[128 * d0], w3 = tws[192 * d0];
            #pragma unroll
            for (int c = 0; c < 4; c++) {
                float y0r,y0i,y1r,y1i,y2r,y2i,y3r,y3i;
                R4BFLY(xr[c][0],xi[c][0], xr[c][1],xi[c][1],
                       xr[c][2],xi[c][2], xr[c][3],xi[c][3],
                       y0r,y0i,y1r,y1i,y2r,y2i,y3r,y3i);
                xr[c][0] = y0r;                   xi[c][0] = y0i;
                xr[c][1] = y1r*w1.x - y1i*w1.y;   xi[c][1] = y1r*w1.y + y1i*w1.x;
                xr[c][2] = y2r*w2.x - y2i*w2.y;   xi[c][2] = y2r*w2.y + y2i*w2.x;
                xr[c][3] = y3r*w3.x - y3i*w3.y;   xi[c][3] = y3r*w3.y + y3i*w3.x;
            }
        }
        #pragma unroll
        for (int c = 0; c < 4; c++)
            #pragma unroll
            for (int d = 0; d < 4; d++) {
                int p = PADI(base + 16 * c + 4 * d);
                mre[p] = xr[c][d];  mim[p] = xi[c][d];
            }
    }
    __syncthreads();

    // ================= PASS C: stage S=1 =================================
    #pragma unroll
    for (int g = 0; g < 4; g++) {
        int o = 16 * t + 4 * g;
        int p0i = PADI(o), p1i = PADI(o + 1), p2i = PADI(o + 2), p3i = PADI(o + 3);
        float x0r = mre[p0i], x0i = mim[p0i];
        float x1r = mre[p1i], x1i = mim[p1i];
        float x2r = mre[p2i], x2i = mim[p2i];
        float x3r = mre[p3i], x3i = mim[p3i];
        float y0r,y0i,y1r,y1i,y2r,y2i,y3r,y3i;
        R4BFLY(x0r,x0i, x1r,x1i, x2r,x2i, x3r,x3i,
               y0r,y0i,y1r,y1i,y2r,y2i,y3r,y3i);
        mre[p0i] = y0r;  mim[p0i] = y0i;
        mre[p1i] = y1r;  mim[p1i] = y1i;
        mre[p2i] = y2r;  mim[p2i] = y2i;
        mre[p3i] = y3r;  mim[p3i] = y3i;
    }
    __syncthreads();
    // X[k] at padded position rev4(k)

    // ---- unpack to registers, then overlay float2 spec on re region ----
    float2 mag[9];
    #pragma unroll
    for (int i = 0; i < 9; i++) {
        int k = t + 64 * i;
        if (k < NBINS) {
            int nk = (N_FFT - k) & (N_FFT - 1);
            int p1 = PADI(rev4(k));
            int p2 = PADI(rev4(nk));
            float rk = mre[p1], ik = mim[p1];
            float rn = mre[p2], in_ = mim[p2];
            float ar = 0.5f * (rk + rn);
            float ai = 0.5f * (ik - in_);
            float br = 0.5f * (ik + in_);
            float bi = 0.5f * (rn - rk);
            mag[i].x = sqrtf(ar * ar + ai * ai);
            mag[i].y = sqrtf(br * br + bi * bi);
        }
    }
    __syncthreads();   // all FFT-output reads done before spec overlay

    float2* spec = reinterpret_cast<float2*>(re);   // 4 units x 544 float2
    {
        float2* sq = spec + q * (FSZ / 2);
        #pragma unroll
        for (int i = 0; i < 9; i++) {
            int k = t + 64 * i;
            if (k < NBINS) sq[k] = mag[i];
        }
        if (t < SUP) sq[NBINS + t] = make_float2(0.0f, 0.0f);
    }
    __syncthreads();

    // ---- sparse mel: thread = (mel m, unit-pair h) ----------------------
    {
        const int m  = tid & (NMELS - 1);
        const int h  = tid >> 7;                 // 0: units 0,1; 1: units 2,3
        const int st = g_start[m];
        const float2* s0 = spec + (2 * h)     * (FSZ / 2) + st;
        const float2* s1 = spec + (2 * h + 1) * (FSZ / 2) + st;
        float a0 = 0.0f, b0 = 0.0f, a1 = 0.0f, b1 = 0.0f;
        #pragma unroll
        for (int j = 0; j < SUP; j++) {
            float fv = g_fbT[j * NMELS + m];
            float2 v0 = s0[j], v1 = s1[j];
            a0 = fmaf(v0.x, fv, a0);  b0 = fmaf(v0.y, fv, b0);
            a1 = fmaf(v1.x, fv, a1);  b1 = fmaf(v1.y, fv, b1);
        }
        const int pbase = (blockIdx.x + blkoff) * 4;
        int fr0 = 2 * (pbase + 2 * h);
        int fr1 = 2 * (pbase + 2 * h + 1);
        size_t rowb = (size_t)b * NFRAMES;
        if (fr0 < NFRAMES)     g_mel[(rowb + fr0)     * NMELS + m] = a0;
        if (fr0 + 1 < NFRAMES) g_mel[(rowb + fr0 + 1) * NMELS + m] = b0;
        if (fr1 < NFRAMES)     g_mel[(rowb + fr1)     * NMELS + m] = a1;
        if (fr1 + 1 < NFRAMES) g_mel[(rowb + fr1 + 1) * NMELS + m] = b1;
    }
}

// ---------------- PCEN stage 1: per-chunk partial EMA -------------------
__global__ __launch_bounds__(128)
void pcen_part1_kernel() {
    const int m = threadIdx.x;
    const int b = blockIdx.x;
    const int c = blockIdx.y;

    const float* p = g_mel + ((size_t)b * NFRAMES + c * LCH) * NMELS + m;

    float state;
    if (c == 0) {
        state = p[0];
        #pragma unroll
        for (int t = 1; t < LCH; t++) {
            float v = p[(size_t)t * NMELS];
            state = fmaf(EMA_A, state, EMA_S * v);
        }
    } else {
        state = 0.0f;
        #pragma unroll
        for (int t = 0; t < LCH; t++) {
            float v = p[(size_t)t * NMELS];
            state = fmaf(EMA_A, state, EMA_S * v);
        }
    }
    g_T[((size_t)b * KCH + c) * NMELS + m] = state;
}

// ---------------- PCEN stage 2: outputs (prefix computed inline) --------
__device__ __forceinline__ float pcen_f(float v, float M) {
    float pw = exp2f(-0.98f * __log2f(M + 1e-6f));
    float y  = fmaf(v, pw, 2.0f);
    return y * rsqrtf(y) - 1.41421356237309515f;
}

__global__ __launch_bounds__(128)
void pcen_part2_kernel(float* __restrict__ out) {
    const int m = threadIdx.x;
    const int b = blockIdx.x;
    const int c = blockIdx.y;

    const int t0 = c * LCH;
    const float* p = g_mel + ((size_t)b * NFRAMES + t0) * NMELS + m;
    float*       o = out  + ((size_t)b * NFRAMES + t0) * NMELS + m;

    if (c == 0) {
        float v0 = p[0];
        float state = v0;
        o[0] = pcen_f(v0, state);
        #pragma unroll
        for (int t = 1; t < LCH; t++) {
            float v = p[(size_t)t * NMELS];
            state = fmaf(EMA_A, state, EMA_S * v);
            o[(size_t)t * NMELS] = pcen_f(v, state);
        }
        return;
    }

    // inline prefix over g_T[0..c-1]
    float A = 1.0f;
    #pragma unroll
    for (int i = 0; i < LCH; i++) A *= EMA_A;
    float state = 0.0f;
    const float* Tp = g_T + (size_t)b * KCH * NMELS + m;
    for (int cc = 0; cc < c; cc++)
        state = fmaf(A, state, Tp[(size_t)cc * NMELS]);

    if (c < KCH - 1) {
        #pragma unroll
        for (int t = 0; t < LCH; t++) {
            float v = p[(size_t)t * NMELS];
            state = fmaf(EMA_A, state, EMA_S * v);
            o[(size_t)t * NMELS] = pcen_f(v, state);
        }
    } else {
        #pragma unroll
        for (int t = 0; t < NFRAMES - (KCH - 1) * LCH; t++) {
            float v = p[(size_t)t * NMELS];
            state = fmaf(EMA_A, state, EMA_S * v);
            o[(size_t)t * NMELS] = pcen_f(v, state);
        }
    }
}

// ---------------- launch ----------------
extern "C" void kernel_launch(void* const* d_in, const int* in_sizes, int n_in,
                              void* d_out, int out_size) {
    const float* x  = (const float*)d_in[0];   // (32, 160000) f32
    const float* fb = (const float*)d_in[1];   // (513, 128)  f32
    float* out = (float*)d_out;                // (32, 626, 128) f32

    prep_tw_kernel<<<4, 256>>>();
    prep_fb_kernel<<<NMELS, 32>>>(fb);
    fft_mel_kernel<<<dim3(NBLK_A, BATCH), 256>>>(x, 0);
    fft_mel_kernel<<<dim3(NBLK_B, BATCH), 256>>>(x, NBLK_A);   // ncu lands here
    pcen_part1_kernel<<<dim3(BATCH, KCH - 1), 128>>>();
    pcen_part2_kernel<<<dim3(BATCH, KCH), 128>>>(out);
}

// round 11
// speedup vs baseline: 2.0000x; 1.0285x over previous
#include <cuda_runtime.h>
#include <math.h>

#define N_FFT   1024
#define HOP     256
#define NBINS   513
#define NMELS   128
#define BATCH   32
#define SIGLEN  160000
#define PAD     512
#define NFRAMES 626
#define NPAIRS  313
#define NBLK_A  40             // split for profiling (ncu lands on launch #4)
#define NBLK_B  39
#define SUP     26

#define KCH     32
#define LCH     20
#define EMA_A   0.975f
#define EMA_S   0.025f

#define PADI(i) ((i) + ((i) >> 4))   // anti-conflict padding (float2 units)
#define FSZ2    1088                 // float2 slots per FFT unit

// ---------------- device scratch ----------------
__device__ float  g_mel[BATCH * NFRAMES * NMELS];
__device__ float  g_T  [BATCH * KCH * NMELS];
__device__ float  g_fbT[SUP * NMELS];
__device__ int    g_start[NMELS];
__device__ float2 g_tw[N_FFT];

// ---------------- prep A: twiddles ----------------
__global__ void prep_tw_kernel() {
    int k = blockIdx.x * 256 + threadIdx.x;
    float ang = -6.283185307179586f * (float)k / (float)N_FFT;
    float s, c;
    sincosf(ang, &s, &c);
    g_tw[k] = make_float2(c, s);
}

// ---------------- prep B: fb compaction ----------------
__global__ void prep_fb_kernel(const float* __restrict__ fb) {
    const int m    = blockIdx.x;
    const int lane = threadIdx.x;

    int first = 0x7fffffff, last = -1;
    for (int f = lane; f < NBINS; f += 32) {
        float v = fb[f * NMELS + m];
        if (v != 0.0f) { first = min(first, f); last = max(last, f); }
    }
    first = __reduce_min_sync(0xffffffffu, first);
    last  = __reduce_max_sync(0xffffffffu, last);

    int st  = (last < 0) ? 0 : first;
    int len = (last < 0) ? 0 : (last - first + 1);
    if (len > SUP) len = SUP;

    if (lane == 0) g_start[m] = st;
    if (lane < SUP) {
        int j = lane;
        g_fbT[j * NMELS + m] = (j < len) ? fb[(st + j) * NMELS + m] : 0.0f;
    }
}

__device__ __forceinline__ int reflect_idx(int src) {
    if (src < 0) src = -src;
    if (src >= SIGLEN) src = 2 * SIGLEN - 2 - src;
    return src;
}

// base-4 digit reversal of 10-bit index
__device__ __forceinline__ int rev4(int k) {
    int r = __brev(k) >> 22;
    return ((r & 0x155) << 1) | ((r & 0x2AA) >> 1);
}

#define R4BFLY(x0r,x0i,x1r,x1i,x2r,x2i,x3r,x3i,                          \
               y0r,y0i,y1r,y1i,y2r,y2i,y3r,y3i)                          \
    {                                                                     \
        float t0r = (x0r)+(x2r), t0i = (x0i)+(x2i);                       \
        float t1r = (x0r)-(x2r), t1i = (x0i)-(x2i);                       \
        float t2r = (x1r)+(x3r), t2i = (x1i)+(x3i);                       \
        float t3r = (x1r)-(x3r), t3i = (x1i)-(x3i);                       \
        y0r = t0r + t2r;  y0i = t0i + t2i;                                \
        y1r = t1r + t3i;  y1i = t1i - t3r;                                \
        y2r = t0r - t2r;  y2i = t0i - t2i;                                \
        y3r = t1r - t3i;  y3i = t1i + t3r;                                \
    }

// ---------------- fft + mel: float2 smem, 3 passes, 4 FFTs/block --------
__global__ __launch_bounds__(256, 3)
void fft_mel_kernel(const float* __restrict__ x, int blkoff) {
    __shared__ float2 cv[4 * FSZ2];      // 34.8 KB (FFT data, later spec)
    __shared__ float2 tws[768];          // 6 KB

    const int tid = threadIdx.x;
    const int q   = tid >> 6;            // FFT unit 0..3
    const int t   = tid & 63;            // thread within FFT
    const int b   = blockIdx.y;
    const int p0  = (blockIdx.x + blkoff) * 4 + q;
    const int pr  = min(p0, NPAIRS - 1);

    const float* xb = x + (size_t)b * SIGLEN;
    float2* mcv = cv + q * FSZ2;

    tws[tid]       = g_tw[tid];
    tws[tid + 256] = g_tw[tid + 256];
    tws[tid + 512] = g_tw[tid + 512];

    // ---- pass A source: straight from gmem into registers --------------
    const int baseA = 2 * pr * HOP - PAD;
    const int baseB = baseA + HOP;
    float xr[4][4], xi[4][4];
    if (pr >= 1 && pr <= 310) {          // fully interior
        #pragma unroll
        for (int a = 0; a < 4; a++)
            #pragma unroll
            for (int bb = 0; bb < 4; bb++) {
                int n = t + 64 * bb + 256 * a;
                xr[a][bb] = xb[baseA + n];
                xi[a][bb] = xb[baseB + n];
            }
    } else {
        #pragma unroll
        for (int a = 0; a < 4; a++)
            #pragma unroll
            for (int bb = 0; bb < 4; bb++) {
                int n = t + 64 * bb + 256 * a;
                xr[a][bb] = xb[reflect_idx(baseA + n)];
                xi[a][bb] = xb[reflect_idx(baseB + n)];
            }
    }
    __syncthreads();   // tws visible

    // ================= PASS A: stages S=256 (a), S=64 (b) ===============
    #pragma unroll
    for (int bb = 0; bb < 4; bb++) {
        float y0r,y0i,y1r,y1i,y2r,y2i,y3r,y3i;
        R4BFLY(xr[0][bb],xi[0][bb], xr[1][bb],xi[1][bb],
               xr[2][bb],xi[2][bb], xr[3][bb],xi[3][bb],
               y0r,y0i,y1r,y1i,y2r,y2i,y3r,y3i);
        int r = t + 64 * bb;
        float2 w1 = tws[r], w2 = tws[2 * r], w3 = tws[3 * r];
        xr[0][bb] = y0r;                      xi[0][bb] = y0i;
        xr[1][bb] = y1r*w1.x - y1i*w1.y;      xi[1][bb] = y1r*w1.y + y1i*w1.x;
        xr[2][bb] = y2r*w2.x - y2i*w2.y;      xi[2][bb] = y2r*w2.y + y2i*w2.x;
        xr[3][bb] = y3r*w3.x - y3i*w3.y;      xi[3][bb] = y3r*w3.y + y3i*w3.x;
    }
    {
        float2 w1 = tws[4 * t], w2 = tws[8 * t], w3 = tws[12 * t];
        #pragma unroll
        for (int a = 0; a < 4; a++) {
            float y0r,y0i,y1r,y1i,y2r,y2i,y3r,y3i;
            R4BFLY(xr[a][0],xi[a][0], xr[a][1],xi[a][1],
                   xr[a][2],xi[a][2], xr[a][3],xi[a][3],
                   y0r,y0i,y1r,y1i,y2r,y2i,y3r,y3i);
            xr[a][0] = y0r;                   xi[a][0] = y0i;
            xr[a][1] = y1r*w1.x - y1i*w1.y;   xi[a][1] = y1r*w1.y + y1i*w1.x;
            xr[a][2] = y2r*w2.x - y2i*w2.y;   xi[a][2] = y2r*w2.y + y2i*w2.x;
            xr[a][3] = y3r*w3.x - y3i*w3.y;   xi[a][3] = y3r*w3.y + y3i*w3.x;
        }
    }
    #pragma unroll
    for (int a = 0; a < 4; a++)
        #pragma unroll
        for (int bb = 0; bb < 4; bb++)
            mcv[PADI(t + 64 * bb + 256 * a)] = make_float2(xr[a][bb], xi[a][bb]);
    __syncthreads();

    // ================= PASS B: stages S=16 (c), S=4 (d) =================
    {
        const int d4 = t >> 4, d3 = (t >> 2) & 3, d0 = t & 3;
        const int base = 256 * d4 + 64 * d3 + d0;
        #pragma unroll
        for (int c = 0; c < 4; c++)
            #pragma unroll
            for (int d = 0; d < 4; d++) {
                float2 v = mcv[PADI(base + 16 * c + 4 * d)];
                xr[c][d] = v.x;  xi[c][d] = v.y;
            }
        #pragma unroll
        for (int d = 0; d < 4; d++) {
            float y0r,y0i,y1r,y1i,y2r,y2i,y3r,y3i;
            R4BFLY(xr[0][d],xi[0][d], xr[1][d],xi[1][d],
                   xr[2][d],xi[2][d], xr[3][d],xi[3][d],
                   y0r,y0i,y1r,y1i,y2r,y2i,y3r,y3i);
            int r = (d0 + 4 * d) * 16;
            float2 w1 = tws[r], w2 = tws[2 * r], w3 = tws[3 * r];
            xr[0][d] = y0r;                   xi[0][d] = y0i;
            xr[1][d] = y1r*w1.x - y1i*w1.y;   xi[1][d] = y1r*w1.y + y1i*w1.x;
            xr[2][d] = y2r*w2.x - y2i*w2.y;   xi[2][d] = y2r*w2.y + y2i*w2.x;
            xr[3][d] = y3r*w3.x - y3i*w3.y;   xi[3][d] = y3r*w3.y + y3i*w3.x;
        }
        {
            float2 w1 = tws[64 * d0], w2 = tws[128 * d0], w3 = tws[192 * d0];
            #pragma unroll
            for (int c = 0; c < 4; c++) {
                float y0r,y0i,y1r,y1i,y2r,y2i,y3r,y3i;
                R4BFLY(xr[c][0],xi[c][0], xr[c][1],xi[c][1],
                       xr[c][2],xi[c][2], xr[c][3],xi[c][3],
                       y0r,y0i,y1r,y1i,y2r,y2i,y3r,y3i);
                xr[c][0] = y0r;                   xi[c][0] = y0i;
                xr[c][1] = y1r*w1.x - y1i*w1.y;   xi[c][1] = y1r*w1.y + y1i*w1.x;
                xr[c][2] = y2r*w2.x - y2i*w2.y;   xi[c][2] = y2r*w2.y + y2i*w2.x;
                xr[c][3] = y3r*w3.x - y3i*w3.y;   xi[c][3] = y3r*w3.y + y3i*w3.x;
            }
        }
        #pragma unroll
        for (int c = 0; c < 4; c++)
            #pragma unroll
            for (int d = 0; d < 4; d++)
                mcv[PADI(base + 16 * c + 4 * d)] = make_float2(xr[c][d], xi[c][d]);
    }
    __syncthreads();

    // ================= PASS C: stage S=1 =================================
    #pragma unroll
    for (int g = 0; g < 4; g++) {
        int o = 16 * t + 4 * g;
        float2 v0 = mcv[PADI(o)],     v1 = mcv[PADI(o + 1)];
        float2 v2 = mcv[PADI(o + 2)], v3 = mcv[PADI(o + 3)];
        float y0r,y0i,y1r,y1i,y2r,y2i,y3r,y3i;
        R4BFLY(v0.x,v0.y, v1.x,v1.y, v2.x,v2.y, v3.x,v3.y,
               y0r,y0i,y1r,y1i,y2r,y2i,y3r,y3i);
        mcv[PADI(o)]     = make_float2(y0r, y0i);
        mcv[PADI(o + 1)] = make_float2(y1r, y1i);
        mcv[PADI(o + 2)] = make_float2(y2r, y2i);
        mcv[PADI(o + 3)] = make_float2(y3r, y3i);
    }
    __syncthreads();
    // X[k] at padded position rev4(k)

    // ---- unpack to registers, then overlay float2 spec ------------------
    float2 mag[9];
    #pragma unroll
    for (int i = 0; i < 9; i++) {
        int k = t + 64 * i;
        if (k < NBINS) {
            int nk = (N_FFT - k) & (N_FFT - 1);
            float2 v1 = mcv[PADI(rev4(k))];
            float2 v2 = mcv[PADI(rev4(nk))];
            float ar = 0.5f * (v1.x + v2.x);
            float ai = 0.5f * (v1.y - v2.y);
            float br = 0.5f * (v1.y + v2.y);
            float bi = 0.5f * (v2.x - v1.x);
            mag[i].x = sqrtf(ar * ar + ai * ai);
            mag[i].y = sqrtf(br * br + bi * bi);
        }
    }
    __syncthreads();   // all FFT-output reads done before spec overlay

    {
        float2* sq = cv + q * FSZ2;      // spec overlays FFT data
        #pragma unroll
        for (int i = 0; i < 9; i++) {
            int k = t + 64 * i;
            if (k < NBINS) sq[k] = mag[i];
        }
        if (t < SUP) sq[NBINS + t] = make_float2(0.0f, 0.0f);
    }
    __syncthreads();

    // ---- sparse mel: thread = (mel m, unit-pair h) ----------------------
    {
        const int m  = tid & (NMELS - 1);
        const int h  = tid >> 7;
        const int st = g_start[m];
        const float2* s0 = cv + (2 * h)     * FSZ2 + st;
        const float2* s1 = cv + (2 * h + 1) * FSZ2 + st;
        float a0 = 0.0f, b0 = 0.0f, a1 = 0.0f, b1 = 0.0f;
        #pragma unroll
        for (int j = 0; j < SUP; j++) {
            float fv = g_fbT[j * NMELS + m];
            float2 v0 = s0[j], v1 = s1[j];
            a0 = fmaf(v0.x, fv, a0);  b0 = fmaf(v0.y, fv, b0);
            a1 = fmaf(v1.x, fv, a1);  b1 = fmaf(v1.y, fv, b1);
        }
        const int pbase = (blockIdx.x + blkoff) * 4;
        int fr0 = 2 * (pbase + 2 * h);
        int fr1 = 2 * (pbase + 2 * h + 1);
        size_t rowb = (size_t)b * NFRAMES;
        if (fr0 < NFRAMES)     g_mel[(rowb + fr0)     * NMELS + m] = a0;
        if (fr0 + 1 < NFRAMES) g_mel[(rowb + fr0 + 1) * NMELS + m] = b0;
        if (fr1 < NFRAMES)     g_mel[(rowb + fr1)     * NMELS + m] = a1;
        if (fr1 + 1 < NFRAMES) g_mel[(rowb + fr1 + 1) * NMELS + m] = b1;
    }
}

// ---------------- PCEN stage 1: per-chunk partial EMA -------------------
__global__ __launch_bounds__(128)
void pcen_part1_kernel() {
    const int m = threadIdx.x;
    const int b = blockIdx.x;
    const int c = blockIdx.y;

    const float* p = g_mel + ((size_t)b * NFRAMES + c * LCH) * NMELS + m;

    float state;
    if (c == 0) {
        state = p[0];
        #pragma unroll
        for (int t = 1; t < LCH; t++) {
            float v = p[(size_t)t * NMELS];
            state = fmaf(EMA_A, state, EMA_S * v);
        }
    } else {
        state = 0.0f;
        #pragma unroll
        for (int t = 0; t < LCH; t++) {
            float v = p[(size_t)t * NMELS];
            state = fmaf(EMA_A, state, EMA_S * v);
        }
    }
    g_T[((size_t)b * KCH + c) * NMELS + m] = state;
}

// ---------------- PCEN stage 2: outputs (prefix inline) -----------------
__device__ __forceinline__ float pcen_f(float v, float M) {
    float pw = exp2f(-0.98f * __log2f(M + 1e-6f));
    float y  = fmaf(v, pw, 2.0f);
    return y * rsqrtf(y) - 1.41421356237309515f;
}

__global__ __launch_bounds__(128)
void pcen_part2_kernel(float* __restrict__ out) {
    const int m = threadIdx.x;
    const int b = blockIdx.x;
    const int c = blockIdx.y;

    const int t0 = c * LCH;
    const float* p = g_mel + ((size_t)b * NFRAMES + t0) * NMELS + m;
    float*       o = out  + ((size_t)b * NFRAMES + t0) * NMELS + m;

    if (c == 0) {
        float v0 = p[0];
        float state = v0;
        o[0] = pcen_f(v0, state);
        #pragma unroll
        for (int t = 1; t < LCH; t++) {
            float v = p[(size_t)t * NMELS];
            state = fmaf(EMA_A, state, EMA_S * v);
            o[(size_t)t * NMELS] = pcen_f(v, state);
        }
        return;
    }

    float A = 1.0f;
    #pragma unroll
    for (int i = 0; i < LCH; i++) A *= EMA_A;
    float state = 0.0f;
    const float* Tp = g_T + (size_t)b * KCH * NMELS + m;
    for (int cc = 0; cc < c; cc++)
        state = fmaf(A, state, Tp[(size_t)cc * NMELS]);

    if (c < KCH - 1) {
        #pragma unroll
        for (int t = 0; t < LCH; t++) {
            float v = p[(size_t)t * NMELS];
            state = fmaf(EMA_A, state, EMA_S * v);
            o[(size_t)t * NMELS] = pcen_f(v, state);
        }
    } else {
        #pragma unroll
        for (int t = 0; t < NFRAMES - (KCH - 1) * LCH; t++) {
            float v = p[(size_t)t * NMELS];
            state = fmaf(EMA_A, state, EMA_S * v);
            o[(size_t)t * NMELS] = pcen_f(v, state);
        }
    }
}

// ---------------- launch ----------------
extern "C" void kernel_launch(void* const* d_in, const int* in_sizes, int n_in,
                              void* d_out, int out_size) {
    const float* x  = (const float*)d_in[0];   // (32, 160000) f32
    const float* fb = (const float*)d_in[1];   // (513, 128)  f32
    float* out = (float*)d_out;                // (32, 626, 128) f32

    prep_tw_kernel<<<4, 256>>>();
    prep_fb_kernel<<<NMELS, 32>>>(fb);
    fft_mel_kernel<<<dim3(NBLK_A, BATCH), 256>>>(x, 0);
    fft_mel_kernel<<<dim3(NBLK_B, BATCH), 256>>>(x, NBLK_A);   // ncu lands here
    pcen_part1_kernel<<<dim3(BATCH, KCH - 1), 128>>>();
    pcen_part2_kernel<<<dim3(BATCH, KCH), 128>>>(out);
}

// round 12
// speedup vs baseline: 2.3246x; 1.1623x over previous
#include <cuda_runtime.h>
#include <math.h>

#define N_FFT   1024
#define HOP     256
#define NBINS   513
#define NMELS   128
#define BATCH   32
#define SIGLEN  160000
#define PAD     512
#define NFRAMES 626
#define NPAIRS  313
#define NBLK_A  40             // split for profiling (ncu lands on launch #4)
#define NBLK_B  39
#define SUP     26

#define KCH     32
#define LCH     20
#define EMA_A   0.975f
#define EMA_S   0.025f

#define PADI(i) ((i) + ((i) >> 4))   // anti-conflict padding (float2 units)
#define FSZ2    1088                 // float2 slots per FFT unit

// ---------------- device scratch ----------------
__device__ float  g_mel[BATCH * NFRAMES * NMELS];
__device__ float  g_T  [BATCH * KCH * NMELS];
__device__ float  g_fbT[SUP * NMELS];
__device__ int    g_start[NMELS];
__device__ float2 g_tw[256];         // W^k, k<256 (only w1 indices needed)

// ---------------- prep A: twiddles ----------------
__global__ void prep_tw_kernel() {
    int k = threadIdx.x;             // 256 threads
    float ang = -6.283185307179586f * (float)k / (float)N_FFT;
    float s, c;
    sincosf(ang, &s, &c);
    g_tw[k] = make_float2(c, s);
}

// ---------------- prep B: fb compaction ----------------
__global__ void prep_fb_kernel(const float* __restrict__ fb) {
    const int m    = blockIdx.x;
    const int lane = threadIdx.x;

    int first = 0x7fffffff, last = -1;
    for (int f = lane; f < NBINS; f += 32) {
        float v = fb[f * NMELS + m];
        if (v != 0.0f) { first = min(first, f); last = max(last, f); }
    }
    first = __reduce_min_sync(0xffffffffu, first);
    last  = __reduce_max_sync(0xffffffffu, last);

    int st  = (last < 0) ? 0 : first;
    int len = (last < 0) ? 0 : (last - first + 1);
    if (len > SUP) len = SUP;

    if (lane == 0) g_start[m] = st;
    if (lane < SUP) {
        int j = lane;
        g_fbT[j * NMELS + m] = (j < len) ? fb[(st + j) * NMELS + m] : 0.0f;
    }
}

__device__ __forceinline__ int reflect_idx(int src) {
    if (src < 0) src = -src;
    if (src >= SIGLEN) src = 2 * SIGLEN - 2 - src;
    return src;
}

// base-4 digit reversal of 8-bit value (4 digits)
__device__ __forceinline__ int rev8(int v) {
    int r = __brev(v) >> 24;
    return ((r & 0x55) << 1) | ((r & 0xAA) >> 1);
}

#define R4BFLY(x0r,x0i,x1r,x1i,x2r,x2i,x3r,x3i,                          \
               y0r,y0i,y1r,y1i,y2r,y2i,y3r,y3i)                          \
    {                                                                     \
        float t0r = (x0r)+(x2r), t0i = (x0i)+(x2i);                       \
        float t1r = (x0r)-(x2r), t1i = (x0i)-(x2i);                       \
        float t2r = (x1r)+(x3r), t2i = (x1i)+(x3i);                       \
        float t3r = (x1r)-(x3r), t3i = (x1i)-(x3i);                       \
        y0r = t0r + t2r;  y0i = t0i + t2i;                                \
        y1r = t1r + t3i;  y1i = t1i - t3r;                                \
        y2r = t0r - t2r;  y2i = t0i - t2i;                                \
        y3r = t1r - t3i;  y3i = t1i + t3r;                                \
    }

// derive w2 = w1^2, w3 = w1*w2 in registers
#define TWSET(w1, w2, w3)                                                 \
    float2 w2 = make_float2(w1.x*w1.x - w1.y*w1.y, 2.0f*w1.x*w1.y);       \
    float2 w3 = make_float2(w1.x*w2.x - w1.y*w2.y, w1.x*w2.y + w1.y*w2.x);

// magnitude pair from X[k] (Z1) and X[N-k] (Z2) of the packed transform
__device__ __forceinline__ float2 packmag(float2 Z1, float2 Z2) {
    float ar = 0.5f * (Z1.x + Z2.x);
    float ai = 0.5f * (Z1.y - Z2.y);
    float br = 0.5f * (Z1.y + Z2.y);
    float bi = 0.5f * (Z2.x - Z1.x);
    return make_float2(sqrtf(ar * ar + ai * ai), sqrtf(br * br + bi * bi));
}

// ---------------- fft + mel: fused last stage + unpack ------------------
__global__ __launch_bounds__(256, 3)
void fft_mel_kernel(const float* __restrict__ x, int blkoff) {
    __shared__ float2 cv[4 * FSZ2];      // 34.8 KB (FFT data, later spec)
    __shared__ float2 tws[256];          // 2 KB

    const int tid = threadIdx.x;
    const int q   = tid >> 6;            // FFT unit 0..3
    const int t   = tid & 63;            // thread within FFT
    const int b   = blockIdx.y;
    const int p0  = (blockIdx.x + blkoff) * 4 + q;
    const int pr  = min(p0, NPAIRS - 1);

    const float* xb = x + (size_t)b * SIGLEN;
    float2* mcv = cv + q * FSZ2;

    if (tid < 256) tws[tid] = g_tw[tid];

    // ---- pass A source: straight from gmem into registers --------------
    const int baseA = 2 * pr * HOP - PAD;
    const int baseB = baseA + HOP;
    float xr[4][4], xi[4][4];
    if (pr >= 1 && pr <= 310) {
        #pragma unroll
        for (int a = 0; a < 4; a++)
            #pragma unroll
            for (int bb = 0; bb < 4; bb++) {
                int n = t + 64 * bb + 256 * a;
                xr[a][bb] = xb[baseA + n];
                xi[a][bb] = xb[baseB + n];
            }
    } else {
        #pragma unroll
        for (int a = 0; a < 4; a++)
            #pragma unroll
            for (int bb = 0; bb < 4; bb++) {
                int n = t + 64 * bb + 256 * a;
                xr[a][bb] = xb[reflect_idx(baseA + n)];
                xi[a][bb] = xb[reflect_idx(baseB + n)];
            }
    }
    __syncthreads();   // tws visible

    // ================= PASS A: stages S=256 (a), S=64 (b) ===============
    #pragma unroll
    for (int bb = 0; bb < 4; bb++) {
        float y0r,y0i,y1r,y1i,y2r,y2i,y3r,y3i;
        R4BFLY(xr[0][bb],xi[0][bb], xr[1][bb],xi[1][bb],
               xr[2][bb],xi[2][bb], xr[3][bb],xi[3][bb],
               y0r,y0i,y1r,y1i,y2r,y2i,y3r,y3i);
        float2 w1 = tws[t + 64 * bb];
        TWSET(w1, w2, w3);
        xr[0][bb] = y0r;                      xi[0][bb] = y0i;
        xr[1][bb] = y1r*w1.x - y1i*w1.y;      xi[1][bb] = y1r*w1.y + y1i*w1.x;
        xr[2][bb] = y2r*w2.x - y2i*w2.y;      xi[2][bb] = y2r*w2.y + y2i*w2.x;
        xr[3][bb] = y3r*w3.x - y3i*w3.y;      xi[3][bb] = y3r*w3.y + y3i*w3.x;
    }
    {
        float2 w1 = tws[4 * t];
        TWSET(w1, w2, w3);
        #pragma unroll
        for (int a = 0; a < 4; a++) {
            float y0r,y0i,y1r,y1i,y2r,y2i,y3r,y3i;
            R4BFLY(xr[a][0],xi[a][0], xr[a][1],xi[a][1],
                   xr[a][2],xi[a][2], xr[a][3],xi[a][3],
                   y0r,y0i,y1r,y1i,y2r,y2i,y3r,y3i);
            xr[a][0] = y0r;                   xi[a][0] = y0i;
            xr[a][1] = y1r*w1.x - y1i*w1.y;   xi[a][1] = y1r*w1.y + y1i*w1.x;
            xr[a][2] = y2r*w2.x - y2i*w2.y;   xi[a][2] = y2r*w2.y + y2i*w2.x;
            xr[a][3] = y3r*w3.x - y3i*w3.y;   xi[a][3] = y3r*w3.y + y3i*w3.x;
        }
    }
    #pragma unroll
    for (int a = 0; a < 4; a++)
        #pragma unroll
        for (int bb = 0; bb < 4; bb++)
            mcv[PADI(t + 64 * bb + 256 * a)] = make_float2(xr[a][bb], xi[a][bb]);
    __syncthreads();

    // ================= PASS B: stages S=16 (c), S=4 (d) =================
    {
        const int d4 = t >> 4, d3 = (t >> 2) & 3, d0 = t & 3;
        const int base = 256 * d4 + 64 * d3 + d0;
        #pragma unroll
        for (int c = 0; c < 4; c++)
            #pragma unroll
            for (int d = 0; d < 4; d++) {
                float2 v = mcv[PADI(base + 16 * c + 4 * d)];
                xr[c][d] = v.x;  xi[c][d] = v.y;
            }
        #pragma unroll
        for (int d = 0; d < 4; d++) {
            float y0r,y0i,y1r,y1i,y2r,y2i,y3r,y3i;
            R4BFLY(xr[0][d],xi[0][d], xr[1][d],xi[1][d],
                   xr[2][d],xi[2][d], xr[3][d],xi[3][d],
                   y0r,y0i,y1r,y1i,y2r,y2i,y3r,y3i);
            float2 w1 = tws[16 * (d0 + 4 * d)];
            TWSET(w1, w2, w3);
            xr[0][d] = y0r;                   xi[0][d] = y0i;
            xr[1][d] = y1r*w1.x - y1i*w1.y;   xi[1][d] = y1r*w1.y + y1i*w1.x;
            xr[2][d] = y2r*w2.x - y2i*w2.y;   xi[2][d] = y2r*w2.y + y2i*w2.x;
            xr[3][d] = y3r*w3.x - y3i*w3.y;   xi[3][d] = y3r*w3.y + y3i*w3.x;
        }
        {
            float2 w1 = tws[64 * d0];
            TWSET(w1, w2, w3);
            #pragma unroll
            for (int c = 0; c < 4; c++) {
                float y0r,y0i,y1r,y1i,y2r,y2i,y3r,y3i;
                R4BFLY(xr[c][0],xi[c][0], xr[c][1],xi[c][1],
                       xr[c][2],xi[c][2], xr[c][3],xi[c][3],
                       y0r,y0i,y1r,y1i,y2r,y2i,y3r,y3i);
                xr[c][0] = y0r;                   xi[c][0] = y0i;
                xr[c][1] = y1r*w1.x - y1i*w1.y;   xi[c][1] = y1r*w1.y + y1i*w1.x;
                xr[c][2] = y2r*w2.x - y2i*w2.y;   xi[c][2] = y2r*w2.y + y2i*w2.x;
                xr[c][3] = y3r*w3.x - y3i*w3.y;   xi[c][3] = y3r*w3.y + y3i*w3.x;
            }
        }
        #pragma unroll
        for (int c = 0; c < 4; c++)
            #pragma unroll
            for (int d = 0; d < 4; d++)
                mcv[PADI(base + 16 * c + 4 * d)] = make_float2(xr[c][d], xi[c][d]);
    }
    __syncthreads();

    // ===== FUSED last stage (S=1) + conjugate unpack, all in registers ==
    // Pre-last-stage group u (positions 4u..4u+3) butterflies to
    // X[v + 256j], v = rev8(u). Partner group u' = rev8(256 - v) supplies
    // all conjugate mirrors. Task v emits bins {v, 256-v, 256+v, 512-v}.
    float2 mag1[4], mag2[4], mag0[3];
    const int v1 = t + 1, v2 = t + 65;   // tasks 1..64 and 65..128
    #pragma unroll
    for (int task = 0; task < 2; task++) {
        const int v  = task ? v2 : v1;
        const int u  = rev8(v & 255);
        const int u2 = rev8((256 - v) & 255);
        float2 a0 = mcv[PADI(4*u)],   a1 = mcv[PADI(4*u+1)];
        float2 a2 = mcv[PADI(4*u+2)], a3 = mcv[PADI(4*u+3)];
        float G0r,G0i,G1r,G1i,G2r,G2i,G3r,G3i;
        R4BFLY(a0.x,a0.y, a1.x,a1.y, a2.x,a2.y, a3.x,a3.y,
               G0r,G0i,G1r,G1i,G2r,G2i,G3r,G3i);
        float2 b0 = mcv[PADI(4*u2)],   b1 = mcv[PADI(4*u2+1)];
        float2 b2 = mcv[PADI(4*u2+2)], b3 = mcv[PADI(4*u2+3)];
        float H0r,H0i,H1r,H1i,H2r,H2i,H3r,H3i;
        R4BFLY(b0.x,b0.y, b1.x,b1.y, b2.x,b2.y, b3.x,b3.y,
               H0r,H0i,H1r,H1i,H2r,H2i,H3r,H3i);
        float2* mg = task ? mag2 : mag1;
        mg[0] = packmag(make_float2(G0r,G0i), make_float2(H3r,H3i)); // bin v
        mg[1] = packmag(make_float2(H0r,H0i), make_float2(G3r,G3i)); // bin 256-v
        mg[2] = packmag(make_float2(G1r,G1i), make_float2(H2r,H2i)); // bin 256+v
        mg[3] = packmag(make_float2(H1r,H1i), make_float2(G2r,G2i)); // bin 512-v
    }
    if (t == 0) {   // group u=0: bins 0, 256, 512
        float2 a0 = mcv[PADI(0)], a1 = mcv[PADI(1)];
        float2 a2 = mcv[PADI(2)], a3 = mcv[PADI(3)];
        float G0r,G0i,G1r,G1i,G2r,G2i,G3r,G3i;
        R4BFLY(a0.x,a0.y, a1.x,a1.y, a2.x,a2.y, a3.x,a3.y,
               G0r,G0i,G1r,G1i,G2r,G2i,G3r,G3i);
        mag0[0] = packmag(make_float2(G0r,G0i), make_float2(G0r,G0i));
        mag0[1] = packmag(make_float2(G1r,G1i), make_float2(G3r,G3i));
        mag0[2] = packmag(make_float2(G2r,G2i), make_float2(G2r,G2i));
    }
    __syncthreads();   // all pass-B reads done before spec overlay

    {
        float2* sq = cv + q * FSZ2;      // spec overlays FFT data (unpadded)
        sq[v1]       = mag1[0];
        sq[256 - v1] = mag1[1];
        sq[256 + v1] = mag1[2];
        sq[512 - v1] = mag1[3];
        sq[v2]       = mag2[0];
        sq[256 - v2] = mag2[1];
        sq[256 + v2] = mag2[2];
        sq[512 - v2] = mag2[3];
        if (t == 0) { sq[0] = mag0[0]; sq[256] = mag0[1]; sq[512] = mag0[2]; }
        if (t < SUP) sq[NBINS + t] = make_float2(0.0f, 0.0f);
    }
    __syncthreads();

    // ---- sparse mel: thread = (mel m, unit-pair h) ----------------------
    {
        const int m  = tid & (NMELS - 1);
        const int h  = tid >> 7;
        const int st = g_start[m];
        const float2* s0 = cv + (2 * h)     * FSZ2 + st;
        const float2* s1 = cv + (2 * h + 1) * FSZ2 + st;
        float a0 = 0.0f, b0 = 0.0f, a1 = 0.0f, b1 = 0.0f;
        #pragma unroll
        for (int j = 0; j < SUP; j++) {
            float fv = g_fbT[j * NMELS + m];
            float2 v0 = s0[j], v1f = s1[j];
            a0 = fmaf(v0.x,  fv, a0);  b0 = fmaf(v0.y,  fv, b0);
            a1 = fmaf(v1f.x, fv, a1);  b1 = fmaf(v1f.y, fv, b1);
        }
        const int pbase = (blockIdx.x + blkoff) * 4;
        int fr0 = 2 * (pbase + 2 * h);
        int fr1 = 2 * (pbase + 2 * h + 1);
        size_t rowb = (size_t)b * NFRAMES;
        if (fr0 < NFRAMES)     g_mel[(rowb + fr0)     * NMELS + m] = a0;
        if (fr0 + 1 < NFRAMES) g_mel[(rowb + fr0 + 1) * NMELS + m] = b0;
        if (fr1 < NFRAMES)     g_mel[(rowb + fr1)     * NMELS + m] = a1;
        if (fr1 + 1 < NFRAMES) g_mel[(rowb + fr1 + 1) * NMELS + m] = b1;
    }
}

// ---------------- PCEN stage 1: per-chunk partial EMA -------------------
__global__ __launch_bounds__(128)
void pcen_part1_kernel() {
    const int m = threadIdx.x;
    const int b = blockIdx.x;
    const int c = blockIdx.y;

    const float* p = g_mel + ((size_t)b * NFRAMES + c * LCH) * NMELS + m;

    float state;
    if (c == 0) {
        state = p[0];
        #pragma unroll
        for (int t = 1; t < LCH; t++) {
            float v = p[(size_t)t * NMELS];
            state = fmaf(EMA_A, state, EMA_S * v);
        }
    } else {
        state = 0.0f;
        #pragma unroll
        for (int t = 0; t < LCH; t++) {
            float v = p[(size_t)t * NMELS];
            state = fmaf(EMA_A, state, EMA_S * v);
        }
    }
    g_T[((size_t)b * KCH + c) * NMELS + m] = state;
}

// ---------------- PCEN stage 2: outputs (prefix inline) -----------------
__device__ __forceinline__ float pcen_f(float v, float M) {
    float pw = exp2f(-0.98f * __log2f(M + 1e-6f));
    float y  = fmaf(v, pw, 2.0f);
    return y * rsqrtf(y) - 1.41421356237309515f;
}

__global__ __launch_bounds__(128)
void pcen_part2_kernel(float* __restrict__ out) {
    const int m = threadIdx.x;
    const int b = blockIdx.x;
    const int c = blockIdx.y;

    const int t0 = c * LCH;
    const float* p = g_mel + ((size_t)b * NFRAMES + t0) * NMELS + m;
    float*       o = out  + ((size_t)b * NFRAMES + t0) * NMELS + m;

    if (c == 0) {
        float v0 = p[0];
        float state = v0;
        o[0] = pcen_f(v0, state);
        #pragma unroll
        for (int t = 1; t < LCH; t++) {
            float v = p[(size_t)t * NMELS];
            state = fmaf(EMA_A, state, EMA_S * v);
            o[(size_t)t * NMELS] = pcen_f(v, state);
        }
        return;
    }

    float A = 1.0f;
    #pragma unroll
    for (int i = 0; i < LCH; i++) A *= EMA_A;
    float state = 0.0f;
    const float* Tp = g_T + (size_t)b * KCH * NMELS + m;
    for (int cc = 0; cc < c; cc++)
        state = fmaf(A, state, Tp[(size_t)cc * NMELS]);

    if (c < KCH - 1) {
        #pragma unroll
        for (int t = 0; t < LCH; t++) {
            float v = p[(size_t)t * NMELS];
            state = fmaf(EMA_A, state, EMA_S * v);
            o[(size_t)t * NMELS] = pcen_f(v, state);
        }
    } else {
        #pragma unroll
        for (int t = 0; t < NFRAMES - (KCH - 1) * LCH; t++) {
            float v = p[(size_t)t * NMELS];
            state = fmaf(EMA_A, state, EMA_S * v);
            o[(size_t)t * NMELS] = pcen_f(v, state);
        }
    }
}

// ---------------- launch ----------------
extern "C" void kernel_launch(void* const* d_in, const int* in_sizes, int n_in,
                              void* d_out, int out_size) {
    const float* x  = (const float*)d_in[0];   // (32, 160000) f32
    const float* fb = (const float*)d_in[1];   // (513, 128)  f32
    float* out = (float*)d_out;                // (32, 626, 128) f32

    prep_tw_kernel<<<1, 256>>>();
    prep_fb_kernel<<<NMELS, 32>>>(fb);
    fft_mel_kernel<<<dim3(NBLK_A, BATCH), 256>>>(x, 0);
    fft_mel_kernel<<<dim3(NBLK_B, BATCH), 256>>>(x, NBLK_A);   // ncu lands here
    pcen_part1_kernel<<<dim3(BATCH, KCH - 1), 128>>>();
    pcen_part2_kernel<<<dim3(BATCH, KCH), 128>>>(out);
}

// round 13
// speedup vs baseline: 2.6511x; 1.1404x over previous
#include <cuda_runtime.h>
#include <math.h>

#define N_FFT   1024
#define HOP     256
#define NBINS   513
#define NMELS   128
#define BATCH   32
#define SIGLEN  160000
#define PAD     512
#define NFRAMES 626
#define NPAIRS  313
#define NBLK_A  40             // split for profiling (ncu lands on launch #4)
#define NBLK_B  39
#define SUP     26

#define KCH     32
#define LCH     20
#define EMA_A   0.975f
#define EMA_S   0.025f

#define PADI(i) ((i) + ((i) >> 4))   // anti-conflict padding (float2 units)
#define FSZ2    1088                 // float2 slots per FFT unit

// ---------------- device scratch ----------------
__device__ float  g_mel[BATCH * NFRAMES * NMELS];
__device__ float  g_T  [BATCH * KCH * NMELS];
__device__ float  g_fbT[SUP * NMELS];
__device__ int    g_start[NMELS];
__device__ int    g_len[NMELS];
__device__ float2 g_tw[256];         // W^k, k<256 (only w1 indices needed)

// ---------------- prep A: twiddles ----------------
__global__ void prep_tw_kernel() {
    int k = threadIdx.x;             // 256 threads
    float ang = -6.283185307179586f * (float)k / (float)N_FFT;
    float s, c;
    sincosf(ang, &s, &c);
    g_tw[k] = make_float2(c, s);
}

// ---------------- prep B: fb compaction ----------------
__global__ void prep_fb_kernel(const float* __restrict__ fb) {
    const int m    = blockIdx.x;
    const int lane = threadIdx.x;

    int first = 0x7fffffff, last = -1;
    for (int f = lane; f < NBINS; f += 32) {
        float v = fb[f * NMELS + m];
        if (v != 0.0f) { first = min(first, f); last = max(last, f); }
    }
    first = __reduce_min_sync(0xffffffffu, first);
    last  = __reduce_max_sync(0xffffffffu, last);

    int st  = (last < 0) ? 0 : first;
    int len = (last < 0) ? 0 : (last - first + 1);
    if (len > SUP) len = SUP;

    if (lane == 0) { g_start[m] = st; g_len[m] = len; }
    if (lane < SUP) {
        int j = lane;
        g_fbT[j * NMELS + m] = (j < len) ? fb[(st + j) * NMELS + m] : 0.0f;
    }
}

__device__ __forceinline__ int reflect_idx(int src) {
    if (src < 0) src = -src;
    if (src >= SIGLEN) src = 2 * SIGLEN - 2 - src;
    return src;
}

// base-4 digit reversal of 8-bit value (4 digits)
__device__ __forceinline__ int rev8(int v) {
    int r = __brev(v) >> 24;
    return ((r & 0x55) << 1) | ((r & 0xAA) >> 1);
}

#define R4BFLY(x0r,x0i,x1r,x1i,x2r,x2i,x3r,x3i,                          \
               y0r,y0i,y1r,y1i,y2r,y2i,y3r,y3i)                          \
    {                                                                     \
        float t0r = (x0r)+(x2r), t0i = (x0i)+(x2i);                       \
        float t1r = (x0r)-(x2r), t1i = (x0i)-(x2i);                       \
        float t2r = (x1r)+(x3r), t2i = (x1i)+(x3i);                       \
        float t3r = (x1r)-(x3r), t3i = (x1i)-(x3i);                       \
        y0r = t0r + t2r;  y0i = t0i + t2i;                                \
        y1r = t1r + t3i;  y1i = t1i - t3r;                                \
        y2r = t0r - t2r;  y2i = t0i - t2i;                                \
        y3r = t1r - t3i;  y3i = t1i + t3r;                                \
    }

// derive w2 = w1^2, w3 = w1*w2 in registers
#define TWSET(w1, w2, w3)                                                 \
    float2 w2 = make_float2(w1.x*w1.x - w1.y*w1.y, 2.0f*w1.x*w1.y);       \
    float2 w3 = make_float2(w1.x*w2.x - w1.y*w2.y, w1.x*w2.y + w1.y*w2.x);

// magnitude pair from X[k] (Z1) and X[N-k] (Z2) of the packed transform
__device__ __forceinline__ float2 packmag(float2 Z1, float2 Z2) {
    float ar = 0.5f * (Z1.x + Z2.x);
    float ai = 0.5f * (Z1.y - Z2.y);
    float br = 0.5f * (Z1.y + Z2.y);
    float bi = 0.5f * (Z2.x - Z1.x);
    return make_float2(sqrtf(ar * ar + ai * ai), sqrtf(br * br + bi * bi));
}

// ---------------- fft + mel ----------------------------------------------
__global__ __launch_bounds__(256, 4)
void fft_mel_kernel(const float* __restrict__ x, int blkoff) {
    __shared__ float2 cv[4 * FSZ2];      // 34.8 KB (FFT data, later spec)
    __shared__ float2 tws[256];          // 2 KB

    const int tid = threadIdx.x;
    const int q   = tid >> 6;            // FFT unit 0..3
    const int t   = tid & 63;            // thread within FFT
    const int b   = blockIdx.y;
    const int p0  = (blockIdx.x + blkoff) * 4 + q;
    const int pr  = min(p0, NPAIRS - 1);

    const float* xb = x + (size_t)b * SIGLEN;
    float2* mcv = cv + q * FSZ2;

    if (tid < 256) tws[tid] = g_tw[tid];

    // ---- pass A source: straight from gmem into registers --------------
    const int baseA = 2 * pr * HOP - PAD;
    const int baseB = baseA + HOP;
    float xr[4][4], xi[4][4];
    if (pr >= 1 && pr <= 310) {
        #pragma unroll
        for (int a = 0; a < 4; a++)
            #pragma unroll
            for (int bb = 0; bb < 4; bb++) {
                int n = t + 64 * bb + 256 * a;
                xr[a][bb] = xb[baseA + n];
                xi[a][bb] = xb[baseB + n];
            }
    } else {
        #pragma unroll
        for (int a = 0; a < 4; a++)
            #pragma unroll
            for (int bb = 0; bb < 4; bb++) {
                int n = t + 64 * bb + 256 * a;
                xr[a][bb] = xb[reflect_idx(baseA + n)];
                xi[a][bb] = xb[reflect_idx(baseB + n)];
            }
    }
    __syncthreads();   // tws visible

    // ================= PASS A: stages S=256 (a), S=64 (b) ===============
    #pragma unroll
    for (int bb = 0; bb < 4; bb++) {
        float y0r,y0i,y1r,y1i,y2r,y2i,y3r,y3i;
        R4BFLY(xr[0][bb],xi[0][bb], xr[1][bb],xi[1][bb],
               xr[2][bb],xi[2][bb], xr[3][bb],xi[3][bb],
               y0r,y0i,y1r,y1i,y2r,y2i,y3r,y3i);
        float2 w1 = tws[t + 64 * bb];
        TWSET(w1, w2, w3);
        xr[0][bb] = y0r;                      xi[0][bb] = y0i;
        xr[1][bb] = y1r*w1.x - y1i*w1.y;      xi[1][bb] = y1r*w1.y + y1i*w1.x;
        xr[2][bb] = y2r*w2.x - y2i*w2.y;      xi[2][bb] = y2r*w2.y + y2i*w2.x;
        xr[3][bb] = y3r*w3.x - y3i*w3.y;      xi[3][bb] = y3r*w3.y + y3i*w3.x;
    }
    {
        float2 w1 = tws[4 * t];
        TWSET(w1, w2, w3);
        #pragma unroll
        for (int a = 0; a < 4; a++) {
            float y0r,y0i,y1r,y1i,y2r,y2i,y3r,y3i;
            R4BFLY(xr[a][0],xi[a][0], xr[a][1],xi[a][1],
                   xr[a][2],xi[a][2], xr[a][3],xi[a][3],
                   y0r,y0i,y1r,y1i,y2r,y2i,y3r,y3i);
            xr[a][0] = y0r;                   xi[a][0] = y0i;
            xr[a][1] = y1r*w1.x - y1i*w1.y;   xi[a][1] = y1r*w1.y + y1i*w1.x;
            xr[a][2] = y2r*w2.x - y2i*w2.y;   xi[a][2] = y2r*w2.y + y2i*w2.x;
            xr[a][3] = y3r*w3.x - y3i*w3.y;   xi[a][3] = y3r*w3.y + y3i*w3.x;
        }
    }
    #pragma unroll
    for (int a = 0; a < 4; a++)
        #pragma unroll
        for (int bb = 0; bb < 4; bb++)
            mcv[PADI(t + 64 * bb + 256 * a)] = make_float2(xr[a][bb], xi[a][bb]);
    __syncthreads();

    // ================= PASS B: stages S=16 (c), S=4 (d) =================
    {
        const int d4 = t >> 4, d3 = (t >> 2) & 3, d0 = t & 3;
        const int base = 256 * d4 + 64 * d3 + d0;
        #pragma unroll
        for (int c = 0; c < 4; c++)
            #pragma unroll
            for (int d = 0; d < 4; d++) {
                float2 v = mcv[PADI(base + 16 * c + 4 * d)];
                xr[c][d] = v.x;  xi[c][d] = v.y;
            }
        #pragma unroll
        for (int d = 0; d < 4; d++) {
            float y0r,y0i,y1r,y1i,y2r,y2i,y3r,y3i;
            R4BFLY(xr[0][d],xi[0][d], xr[1][d],xi[1][d],
                   xr[2][d],xi[2][d], xr[3][d],xi[3][d],
                   y0r,y0i,y1r,y1i,y2r,y2i,y3r,y3i);
            float2 w1 = tws[16 * (d0 + 4 * d)];
            TWSET(w1, w2, w3);
            xr[0][d] = y0r;                   xi[0][d] = y0i;
            xr[1][d] = y1r*w1.x - y1i*w1.y;   xi[1][d] = y1r*w1.y + y1i*w1.x;
            xr[2][d] = y2r*w2.x - y2i*w2.y;   xi[2][d] = y2r*w2.y + y2i*w2.x;
            xr[3][d] = y3r*w3.x - y3i*w3.y;   xi[3][d] = y3r*w3.y + y3i*w3.x;
        }
        {
            float2 w1 = tws[64 * d0];
            TWSET(w1, w2, w3);
            #pragma unroll
            for (int c = 0; c < 4; c++) {
                float y0r,y0i,y1r,y1i,y2r,y2i,y3r,y3i;
                R4BFLY(xr[c][0],xi[c][0], xr[c][1],xi[c][1],
                       xr[c][2],xi[c][2], xr[c][3],xi[c][3],
                       y0r,y0i,y1r,y1i,y2r,y2i,y3r,y3i);
                xr[c][0] = y0r;                   xi[c][0] = y0i;
                xr[c][1] = y1r*w1.x - y1i*w1.y;   xi[c][1] = y1r*w1.y + y1i*w1.x;
                xr[c][2] = y2r*w2.x - y2i*w2.y;   xi[c][2] = y2r*w2.y + y2i*w2.x;
                xr[c][3] = y3r*w3.x - y3i*w3.y;   xi[c][3] = y3r*w3.y + y3i*w3.x;
            }
        }
        #pragma unroll
        for (int c = 0; c < 4; c++)
            #pragma unroll
            for (int d = 0; d < 4; d++)
                mcv[PADI(base + 16 * c + 4 * d)] = make_float2(xr[c][d], xi[c][d]);
    }
    __syncthreads();

    // ===== FUSED last stage (S=1) + conjugate unpack, all in registers ==
    float2 mag1[4], mag2[4], mag0[3];
    const int v1 = t + 1, v2 = t + 65;   // tasks 1..64 and 65..128
    #pragma unroll
    for (int task = 0; task < 2; task++) {
        const int v  = task ? v2 : v1;
        const int u  = rev8(v & 255);
        const int u2 = rev8((256 - v) & 255);
        float2 a0 = mcv[PADI(4*u)],   a1 = mcv[PADI(4*u+1)];
        float2 a2 = mcv[PADI(4*u+2)], a3 = mcv[PADI(4*u+3)];
        float G0r,G0i,G1r,G1i,G2r,G2i,G3r,G3i;
        R4BFLY(a0.x,a0.y, a1.x,a1.y, a2.x,a2.y, a3.x,a3.y,
               G0r,G0i,G1r,G1i,G2r,G2i,G3r,G3i);
        float2 b0 = mcv[PADI(4*u2)],   b1 = mcv[PADI(4*u2+1)];
        float2 b2 = mcv[PADI(4*u2+2)], b3 = mcv[PADI(4*u2+3)];
        float H0r,H0i,H1r,H1i,H2r,H2i,H3r,H3i;
        R4BFLY(b0.x,b0.y, b1.x,b1.y, b2.x,b2.y, b3.x,b3.y,
               H0r,H0i,H1r,H1i,H2r,H2i,H3r,H3i);
        float2* mg = task ? mag2 : mag1;
        mg[0] = packmag(make_float2(G0r,G0i), make_float2(H3r,H3i)); // bin v
        mg[1] = packmag(make_float2(H0r,H0i), make_float2(G3r,G3i)); // bin 256-v
        mg[2] = packmag(make_float2(G1r,G1i), make_float2(H2r,H2i)); // bin 256+v
        mg[3] = packmag(make_float2(H1r,H1i), make_float2(G2r,G2i)); // bin 512-v
    }
    if (t == 0) {   // group u=0: bins 0, 256, 512
        float2 a0 = mcv[PADI(0)], a1 = mcv[PADI(1)];
        float2 a2 = mcv[PADI(2)], a3 = mcv[PADI(3)];
        float G0r,G0i,G1r,G1i,G2r,G2i,G3r,G3i;
        R4BFLY(a0.x,a0.y, a1.x,a1.y, a2.x,a2.y, a3.x,a3.y,
               G0r,G0i,G1r,G1i,G2r,G2i,G3r,G3i);
        mag0[0] = packmag(make_float2(G0r,G0i), make_float2(G0r,G0i));
        mag0[1] = packmag(make_float2(G1r,G1i), make_float2(G3r,G3i));
        mag0[2] = packmag(make_float2(G2r,G2i), make_float2(G2r,G2i));
    }
    __syncthreads();   // all pass-B reads done before spec overlay

    {
        float2* sq = cv + q * FSZ2;      // spec overlays FFT data (unpadded)
        sq[v1]       = mag1[0];
        sq[256 - v1] = mag1[1];
        sq[256 + v1] = mag1[2];
        sq[512 - v1] = mag1[3];
        sq[v2]       = mag2[0];
        sq[256 - v2] = mag2[1];
        sq[256 + v2] = mag2[2];
        sq[512 - v2] = mag2[3];
        if (t == 0) { sq[0] = mag0[0]; sq[256] = mag0[1]; sq[512] = mag0[2]; }
        if (t < SUP) sq[NBINS + t] = make_float2(0.0f, 0.0f);
    }
    __syncthreads();

    // ---- sparse mel: exact support length per mel -----------------------
    {
        const int m   = tid & (NMELS - 1);
        const int h   = tid >> 7;
        const int st  = g_start[m];
        const int len = g_len[m];
        const float2* s0 = cv + (2 * h)     * FSZ2 + st;
        const float2* s1 = cv + (2 * h + 1) * FSZ2 + st;
        float a0 = 0.0f, b0 = 0.0f, a1 = 0.0f, b1 = 0.0f;
        #pragma unroll 2
        for (int j = 0; j < len; j++) {
            float fv = g_fbT[j * NMELS + m];
            float2 v0 = s0[j], v1f = s1[j];
            a0 = fmaf(v0.x,  fv, a0);  b0 = fmaf(v0.y,  fv, b0);
            a1 = fmaf(v1f.x, fv, a1);  b1 = fmaf(v1f.y, fv, b1);
        }
        const int pbase = (blockIdx.x + blkoff) * 4;
        int fr0 = 2 * (pbase + 2 * h);
        int fr1 = 2 * (pbase + 2 * h + 1);
        size_t rowb = (size_t)b * NFRAMES;
        if (fr0 < NFRAMES)     g_mel[(rowb + fr0)     * NMELS + m] = a0;
        if (fr0 + 1 < NFRAMES) g_mel[(rowb + fr0 + 1) * NMELS + m] = b0;
        if (fr1 < NFRAMES)     g_mel[(rowb + fr1)     * NMELS + m] = a1;
        if (fr1 + 1 < NFRAMES) g_mel[(rowb + fr1 + 1) * NMELS + m] = b1;
    }
}

// ---------------- PCEN stage 1: per-chunk partial EMA -------------------
__global__ __launch_bounds__(128)
void pcen_part1_kernel() {
    const int m = threadIdx.x;
    const int b = blockIdx.x;
    const int c = blockIdx.y;

    const float* p = g_mel + ((size_t)b * NFRAMES + c * LCH) * NMELS + m;

    float state;
    if (c == 0) {
        state = p[0];
        #pragma unroll
        for (int t = 1; t < LCH; t++) {
            float v = p[(size_t)t * NMELS];
            state = fmaf(EMA_A, state, EMA_S * v);
        }
    } else {
        state = 0.0f;
        #pragma unroll
        for (int t = 0; t < LCH; t++) {
            float v = p[(size_t)t * NMELS];
            state = fmaf(EMA_A, state, EMA_S * v);
        }
    }
    g_T[((size_t)b * KCH + c) * NMELS + m] = state;
}

// ---------------- PCEN stage 2: outputs (prefix inline) -----------------
__device__ __forceinline__ float pcen_f(float v, float M) {
    float pw = exp2f(-0.98f * __log2f(M + 1e-6f));
    float y  = fmaf(v, pw, 2.0f);
    return y * rsqrtf(y) - 1.41421356237309515f;
}

__global__ __launch_bounds__(128)
void pcen_part2_kernel(float* __restrict__ out) {
    const int m = threadIdx.x;
    const int b = blockIdx.x;
    const int c = blockIdx.y;

    const int t0 = c * LCH;
    const float* p = g_mel + ((size_t)b * NFRAMES + t0) * NMELS + m;
    float*       o = out  + ((size_t)b * NFRAMES + t0) * NMELS + m;

    if (c == 0) {
        float v0 = p[0];
        float state = v0;
        o[0] = pcen_f(v0, state);
        #pragma unroll
        for (int t = 1; t < LCH; t++) {
            float v = p[(size_t)t * NMELS];
            state = fmaf(EMA_A, state, EMA_S * v);
            o[(size_t)t * NMELS] = pcen_f(v, state);
        }
        return;
    }

    float A = 1.0f;
    #pragma unroll
    for (int i = 0; i < LCH; i++) A *= EMA_A;
    float state = 0.0f;
    const float* Tp = g_T + (size_t)b * KCH * NMELS + m;
    for (int cc = 0; cc < c; cc++)
        state = fmaf(A, state, Tp[(size_t)cc * NMELS]);

    if (c < KCH - 1) {
        #pragma unroll
        for (int t = 0; t < LCH; t++) {
            float v = p[(size_t)t * NMELS];
            state = fmaf(EMA_A, state, EMA_S * v);
            o[(size_t)t * NMELS] = pcen_f(v, state);
        }
    } else {
        #pragma unroll
        for (int t = 0; t < NFRAMES - (KCH - 1) * LCH; t++) {
            float v = p[(size_t)t * NMELS];
            state = fmaf(EMA_A, state, EMA_S * v);
            o[(size_t)t * NMELS] = pcen_f(v, state);
        }
    }
}

// ---------------- launch ----------------
extern "C" void kernel_launch(void* const* d_in, const int* in_sizes, int n_in,
                              void* d_out, int out_size) {
    const float* x  = (const float*)d_in[0];   // (32, 160000) f32
    const float* fb = (const float*)d_in[1];   // (513, 128)  f32
    float* out = (float*)d_out;                // (32, 626, 128) f32

    prep_tw_kernel<<<1, 256>>>();
    prep_fb_kernel<<<NMELS, 32>>>(fb);
    fft_mel_kernel<<<dim3(NBLK_A, BATCH), 256>>>(x, 0);
    fft_mel_kernel<<<dim3(NBLK_B, BATCH), 256>>>(x, NBLK_A);   // ncu lands here
    pcen_part1_kernel<<<dim3(BATCH, KCH - 1), 128>>>();
    pcen_part2_kernel<<<dim3(BATCH, KCH), 128>>>(out);
}

// round 14
// speedup vs baseline: 2.9526x; 1.1137x over previous
#include <cuda_runtime.h>
#include <math.h>

#define N_FFT   1024
#define HOP     256
#define NBINS   513
#define NMELS   128
#define BATCH   32
#define SIGLEN  160000
#define PAD     512
#define NFRAMES 626
#define NPAIRS  313
#define NBLK    79
#define SUP     26

#define KCH     32
#define LCH     20
#define EMA_A   0.975f
#define EMA_S   0.025f

#define PADI(i) ((i) + ((i) >> 4))   // anti-conflict padding (float2 units)
#define FSZ2    1088                 // float2 slots per FFT unit

// unit-scoped barrier: 64 threads of FFT unit q (ids 1..4)
#define UNIT_BAR(q) asm volatile("bar.sync %0, %1;" :: "r"((q) + 1), "r"(64) : "memory")

// ---------------- device scratch ----------------
__device__ float  g_mel[BATCH * NFRAMES * NMELS];
__device__ float  g_T  [BATCH * KCH * NMELS];
__device__ float  g_fbT[SUP * NMELS];
__device__ int    g_start[NMELS];
__device__ int    g_len[NMELS];
__device__ float2 g_tw[256];         // W^k, k<256

// ---------------- prep A: twiddles ----------------
__global__ void prep_tw_kernel() {
    int k = threadIdx.x;             // 256 threads
    float ang = -6.283185307179586f * (float)k / (float)N_FFT;
    float s, c;
    sincosf(ang, &s, &c);
    g_tw[k] = make_float2(c, s);
}

// ---------------- prep B: fb compaction ----------------
__global__ void prep_fb_kernel(const float* __restrict__ fb) {
    const int m    = blockIdx.x;
    const int lane = threadIdx.x;

    int first = 0x7fffffff, last = -1;
    for (int f = lane; f < NBINS; f += 32) {
        float v = fb[f * NMELS + m];
        if (v != 0.0f) { first = min(first, f); last = max(last, f); }
    }
    first = __reduce_min_sync(0xffffffffu, first);
    last  = __reduce_max_sync(0xffffffffu, last);

    int st  = (last < 0) ? 0 : first;
    int len = (last < 0) ? 0 : (last - first + 1);
    if (len > SUP) len = SUP;

    if (lane == 0) { g_start[m] = st; g_len[m] = len; }
    if (lane < SUP) {
        int j = lane;
        g_fbT[j * NMELS + m] = (j < len) ? fb[(st + j) * NMELS + m] : 0.0f;
    }
}

__device__ __forceinline__ int reflect_idx(int src) {
    if (src < 0) src = -src;
    if (src >= SIGLEN) src = 2 * SIGLEN - 2 - src;
    return src;
}

// base-4 digit reversal of 8-bit value
__device__ __forceinline__ int rev8(int v) {
    int r = __brev(v) >> 24;
    return ((r & 0x55) << 1) | ((r & 0xAA) >> 1);
}

#define R4BFLY(x0r,x0i,x1r,x1i,x2r,x2i,x3r,x3i,                          \
               y0r,y0i,y1r,y1i,y2r,y2i,y3r,y3i)                          \
    {                                                                     \
        float t0r = (x0r)+(x2r), t0i = (x0i)+(x2i);                       \
        float t1r = (x0r)-(x2r), t1i = (x0i)-(x2i);                       \
        float t2r = (x1r)+(x3r), t2i = (x1i)+(x3i);                       \
        float t3r = (x1r)-(x3r), t3i = (x1i)-(x3i);                       \
        y0r = t0r + t2r;  y0i = t0i + t2i;                                \
        y1r = t1r + t3i;  y1i = t1i - t3r;                                \
        y2r = t0r - t2r;  y2i = t0i - t2i;                                \
        y3r = t1r - t3i;  y3i = t1i + t3r;                                \
    }

#define TWSET(w1, w2, w3)                                                 \
    float2 w2 = make_float2(w1.x*w1.x - w1.y*w1.y, 2.0f*w1.x*w1.y);       \
    float2 w3 = make_float2(w1.x*w2.x - w1.y*w2.y, w1.x*w2.y + w1.y*w2.x);

__device__ __forceinline__ float2 packmag(float2 Z1, float2 Z2) {
    float ar = 0.5f * (Z1.x + Z2.x);
    float ai = 0.5f * (Z1.y - Z2.y);
    float br = 0.5f * (Z1.y + Z2.y);
    float bi = 0.5f * (Z2.x - Z1.x);
    return make_float2(sqrtf(ar * ar + ai * ai), sqrtf(br * br + bi * bi));
}

// ---------------- fft + mel ----------------------------------------------
__global__ __launch_bounds__(256, 4)
void fft_mel_kernel(const float* __restrict__ x) {
    __shared__ float2 cv[4 * FSZ2];      // 34.8 KB
    __shared__ float2 tws[256];          // 2 KB

    const int tid = threadIdx.x;
    const int q   = tid >> 6;            // FFT unit 0..3
    const int t   = tid & 63;
    const int b   = blockIdx.y;
    const int p0  = blockIdx.x * 4 + q;
    const int pr  = min(p0, NPAIRS - 1);

    const float* xb = x + (size_t)b * SIGLEN;
    float2* mcv = cv + q * FSZ2;

    if (tid < 256) tws[tid] = g_tw[tid];

    // ---- pass A source: straight from gmem into registers --------------
    const int baseA = 2 * pr * HOP - PAD;
    const int baseB = baseA + HOP;
    float xr[4][4], xi[4][4];
    if (pr >= 1 && pr <= 310) {
        #pragma unroll
        for (int a = 0; a < 4; a++)
            #pragma unroll
            for (int bb = 0; bb < 4; bb++) {
                int n = t + 64 * bb + 256 * a;
                xr[a][bb] = xb[baseA + n];
                xi[a][bb] = xb[baseB + n];
            }
    } else {
        #pragma unroll
        for (int a = 0; a < 4; a++)
            #pragma unroll
            for (int bb = 0; bb < 4; bb++) {
                int n = t + 64 * bb + 256 * a;
                xr[a][bb] = xb[reflect_idx(baseA + n)];
                xi[a][bb] = xb[reflect_idx(baseB + n)];
            }
    }
    __syncthreads();   // tws visible to all units

    // ================= PASS A: stages S=256 (a), S=64 (b) ===============
    #pragma unroll
    for (int bb = 0; bb < 4; bb++) {
        float y0r,y0i,y1r,y1i,y2r,y2i,y3r,y3i;
        R4BFLY(xr[0][bb],xi[0][bb], xr[1][bb],xi[1][bb],
               xr[2][bb],xi[2][bb], xr[3][bb],xi[3][bb],
               y0r,y0i,y1r,y1i,y2r,y2i,y3r,y3i);
        float2 w1 = tws[t + 64 * bb];
        TWSET(w1, w2, w3);
        xr[0][bb] = y0r;                      xi[0][bb] = y0i;
        xr[1][bb] = y1r*w1.x - y1i*w1.y;      xi[1][bb] = y1r*w1.y + y1i*w1.x;
        xr[2][bb] = y2r*w2.x - y2i*w2.y;      xi[2][bb] = y2r*w2.y + y2i*w2.x;
        xr[3][bb] = y3r*w3.x - y3i*w3.y;      xi[3][bb] = y3r*w3.y + y3i*w3.x;
    }
    {
        float2 w1 = tws[4 * t];
        TWSET(w1, w2, w3);
        #pragma unroll
        for (int a = 0; a < 4; a++) {
            float y0r,y0i,y1r,y1i,y2r,y2i,y3r,y3i;
            R4BFLY(xr[a][0],xi[a][0], xr[a][1],xi[a][1],
                   xr[a][2],xi[a][2], xr[a][3],xi[a][3],
                   y0r,y0i,y1r,y1i,y2r,y2i,y3r,y3i);
            xr[a][0] = y0r;                   xi[a][0] = y0i;
            xr[a][1] = y1r*w1.x - y1i*w1.y;   xi[a][1] = y1r*w1.y + y1i*w1.x;
            xr[a][2] = y2r*w2.x - y2i*w2.y;   xi[a][2] = y2r*w2.y + y2i*w2.x;
            xr[a][3] = y3r*w3.x - y3i*w3.y;   xi[a][3] = y3r*w3.y + y3i*w3.x;
        }
    }
    #pragma unroll
    for (int a = 0; a < 4; a++)
        #pragma unroll
        for (int bb = 0; bb < 4; bb++)
            mcv[PADI(t + 64 * bb + 256 * a)] = make_float2(xr[a][bb], xi[a][bb]);
    UNIT_BAR(q);

    // ================= PASS B: stages S=16 (c), S=4 (d) =================
    {
        const int d4 = t >> 4, d3 = (t >> 2) & 3, d0 = t & 3;
        const int base = 256 * d4 + 64 * d3 + d0;
        #pragma unroll
        for (int c = 0; c < 4; c++)
            #pragma unroll
            for (int d = 0; d < 4; d++) {
                float2 v = mcv[PADI(base + 16 * c + 4 * d)];
                xr[c][d] = v.x;  xi[c][d] = v.y;
            }
        #pragma unroll
        for (int d = 0; d < 4; d++) {
            float y0r,y0i,y1r,y1i,y2r,y2i,y3r,y3i;
            R4BFLY(xr[0][d],xi[0][d], xr[1][d],xi[1][d],
                   xr[2][d],xi[2][d], xr[3][d],xi[3][d],
                   y0r,y0i,y1r,y1i,y2r,y2i,y3r,y3i);
            float2 w1 = tws[16 * (d0 + 4 * d)];
            TWSET(w1, w2, w3);
            xr[0][d] = y0r;                   xi[0][d] = y0i;
            xr[1][d] = y1r*w1.x - y1i*w1.y;   xi[1][d] = y1r*w1.y + y1i*w1.x;
            xr[2][d] = y2r*w2.x - y2i*w2.y;   xi[2][d] = y2r*w2.y + y2i*w2.x;
            xr[3][d] = y3r*w3.x - y3i*w3.y;   xi[3][d] = y3r*w3.y + y3i*w3.x;
        }
        {
            float2 w1 = tws[64 * d0];
            TWSET(w1, w2, w3);
            #pragma unroll
            for (int c = 0; c < 4; c++) {
                float y0r,y0i,y1r,y1i,y2r,y2i,y3r,y3i;
                R4BFLY(xr[c][0],xi[c][0], xr[c][1],xi[c][1],
                       xr[c][2],xi[c][2], xr[c][3],xi[c][3],
                       y0r,y0i,y1r,y1i,y2r,y2i,y3r,y3i);
                xr[c][0] = y0r;                   xi[c][0] = y0i;
                xr[c][1] = y1r*w1.x - y1i*w1.y;   xi[c][1] = y1r*w1.y + y1i*w1.x;
                xr[c][2] = y2r*w2.x - y2i*w2.y;   xi[c][2] = y2r*w2.y + y2i*w2.x;
                xr[c][3] = y3r*w3.x - y3i*w3.y;   xi[c][3] = y3r*w3.y + y3i*w3.x;
            }
        }
        #pragma unroll
        for (int c = 0; c < 4; c++)
            #pragma unroll
            for (int d = 0; d < 4; d++)
                mcv[PADI(base + 16 * c + 4 * d)] = make_float2(xr[c][d], xi[c][d]);
    }
    UNIT_BAR(q);

    // ===== FUSED last stage (S=1) + conjugate unpack =====================
    float2 mag1[4], mag2[4], mag0[3];
    const int v1 = t + 1, v2 = t + 65;
    #pragma unroll
    for (int task = 0; task < 2; task++) {
        const int v  = task ? v2 : v1;
        const int u  = rev8(v & 255);
        const int u2 = rev8((256 - v) & 255);
        float2 a0 = mcv[PADI(4*u)],   a1 = mcv[PADI(4*u+1)];
        float2 a2 = mcv[PADI(4*u+2)], a3 = mcv[PADI(4*u+3)];
        float G0r,G0i,G1r,G1i,G2r,G2i,G3r,G3i;
        R4BFLY(a0.x,a0.y, a1.x,a1.y, a2.x,a2.y, a3.x,a3.y,
               G0r,G0i,G1r,G1i,G2r,G2i,G3r,G3i);
        float2 b0 = mcv[PADI(4*u2)],   b1 = mcv[PADI(4*u2+1)];
        float2 b2 = mcv[PADI(4*u2+2)], b3 = mcv[PADI(4*u2+3)];
        float H0r,H0i,H1r,H1i,H2r,H2i,H3r,H3i;
        R4BFLY(b0.x,b0.y, b1.x,b1.y, b2.x,b2.y, b3.x,b3.y,
               H0r,H0i,H1r,H1i,H2r,H2i,H3r,H3i);
        float2* mg = task ? mag2 : mag1;
        mg[0] = packmag(make_float2(G0r,G0i), make_float2(H3r,H3i));
        mg[1] = packmag(make_float2(H0r,H0i), make_float2(G3r,G3i));
        mg[2] = packmag(make_float2(G1r,G1i), make_float2(H2r,H2i));
        mg[3] = packmag(make_float2(H1r,H1i), make_float2(G2r,G2i));
    }
    if (t == 0) {
        float2 a0 = mcv[PADI(0)], a1 = mcv[PADI(1)];
        float2 a2 = mcv[PADI(2)], a3 = mcv[PADI(3)];
        float G0r,G0i,G1r,G1i,G2r,G2i,G3r,G3i;
        R4BFLY(a0.x,a0.y, a1.x,a1.y, a2.x,a2.y, a3.x,a3.y,
               G0r,G0i,G1r,G1i,G2r,G2i,G3r,G3i);
        mag0[0] = packmag(make_float2(G0r,G0i), make_float2(G0r,G0i));
        mag0[1] = packmag(make_float2(G1r,G1i), make_float2(G3r,G3i));
        mag0[2] = packmag(make_float2(G2r,G2i), make_float2(G2r,G2i));
    }
    UNIT_BAR(q);   // unit's pass-B reads done before spec overlay

    {
        float2* sq = cv + q * FSZ2;
        sq[v1]       = mag1[0];
        sq[256 - v1] = mag1[1];
        sq[256 + v1] = mag1[2];
        sq[512 - v1] = mag1[3];
        sq[v2]       = mag2[0];
        sq[256 - v2] = mag2[1];
        sq[256 + v2] = mag2[2];
        sq[512 - v2] = mag2[3];
        if (t == 0) { sq[0] = mag0[0]; sq[256] = mag0[1]; sq[512] = mag0[2]; }
        if (t < SUP) sq[NBINS + t] = make_float2(0.0f, 0.0f);
    }
    __syncthreads();   // block-wide: mel reads across all units

    // ---- sparse mel: exact support length per mel -----------------------
    {
        const int m   = tid & (NMELS - 1);
        const int h   = tid >> 7;
        const int st  = g_start[m];
        const int len = g_len[m];
        const float2* s0 = cv + (2 * h)     * FSZ2 + st;
        const float2* s1 = cv + (2 * h + 1) * FSZ2 + st;
        float a0 = 0.0f, b0 = 0.0f, a1 = 0.0f, b1 = 0.0f;
        #pragma unroll 2
        for (int j = 0; j < len; j++) {
            float fv = g_fbT[j * NMELS + m];
            float2 v0 = s0[j], v1f = s1[j];
            a0 = fmaf(v0.x,  fv, a0);  b0 = fmaf(v0.y,  fv, b0);
            a1 = fmaf(v1f.x, fv, a1);  b1 = fmaf(v1f.y, fv, b1);
        }
        const int pbase = blockIdx.x * 4;
        int fr0 = 2 * (pbase + 2 * h);
        int fr1 = 2 * (pbase + 2 * h + 1);
        size_t rowb = (size_t)b * NFRAMES;
        if (fr0 < NFRAMES)     g_mel[(rowb + fr0)     * NMELS + m] = a0;
        if (fr0 + 1 < NFRAMES) g_mel[(rowb + fr0 + 1) * NMELS + m] = b0;
        if (fr1 < NFRAMES)     g_mel[(rowb + fr1)     * NMELS + m] = a1;
        if (fr1 + 1 < NFRAMES) g_mel[(rowb + fr1 + 1) * NMELS + m] = b1;
    }
}

// ---------------- PCEN stage 1: per-chunk partial EMA -------------------
__global__ __launch_bounds__(128)
void pcen_part1_kernel() {
    const int m = threadIdx.x;
    const int b = blockIdx.x;
    const int c = blockIdx.y;

    const float* p = g_mel + ((size_t)b * NFRAMES + c * LCH) * NMELS + m;

    float state;
    if (c == 0) {
        state = p[0];
        #pragma unroll
        for (int t = 1; t < LCH; t++) {
            float v = p[(size_t)t * NMELS];
            state = fmaf(EMA_A, state, EMA_S * v);
        }
    } else {
        state = 0.0f;
        #pragma unroll
        for (int t = 0; t < LCH; t++) {
            float v = p[(size_t)t * NMELS];
            state = fmaf(EMA_A, state, EMA_S * v);
        }
    }
    g_T[((size_t)b * KCH + c) * NMELS + m] = state;
}

// ---------------- PCEN stage 2: outputs (prefix inline) -----------------
__device__ __forceinline__ float pcen_f(float v, float M) {
    float pw = exp2f(-0.98f * __log2f(M + 1e-6f));
    float y  = fmaf(v, pw, 2.0f);
    return y * rsqrtf(y) - 1.41421356237309515f;
}

__global__ __launch_bounds__(128)
void pcen_part2_kernel(float* __restrict__ out) {
    const int m = threadIdx.x;
    const int b = blockIdx.x;
    const int c = blockIdx.y;

    const int t0 = c * LCH;
    const float* p = g_mel + ((size_t)b * NFRAMES + t0) * NMELS + m;
    float*       o = out  + ((size_t)b * NFRAMES + t0) * NMELS + m;

    if (c == 0) {
        float v0 = p[0];
        float state = v0;
        o[0] = pcen_f(v0, state);
        #pragma unroll
        for (int t = 1; t < LCH; t++) {
            float v = p[(size_t)t * NMELS];
            state = fmaf(EMA_A, state, EMA_S * v);
            o[(size_t)t * NMELS] = pcen_f(v, state);
        }
        return;
    }

    float A = 1.0f;
    #pragma unroll
    for (int i = 0; i < LCH; i++) A *= EMA_A;
    float state = 0.0f;
    const float* Tp = g_T + (size_t)b * KCH * NMELS + m;
    for (int cc = 0; cc < c; cc++)
        state = fmaf(A, state, Tp[(size_t)cc * NMELS]);

    if (c < KCH - 1) {
        #pragma unroll
        for (int t = 0; t < LCH; t++) {
            float v = p[(size_t)t * NMELS];
            state = fmaf(EMA_A, state, EMA_S * v);
            o[(size_t)t * NMELS] = pcen_f(v, state);
        }
    } else {
        #pragma unroll
        for (int t = 0; t < NFRAMES - (KCH - 1) * LCH; t++) {
            float v = p[(size_t)t * NMELS];
            state = fmaf(EMA_A, state, EMA_S * v);
            o[(size_t)t * NMELS] = pcen_f(v, state);
        }
    }
}

// ---------------- launch ----------------
extern "C" void kernel_launch(void* const* d_in, const int* in_sizes, int n_in,
                              void* d_out, int out_size) {
    const float* x  = (const float*)d_in[0];   // (32, 160000) f32
    const float* fb = (const float*)d_in[1];   // (513, 128)  f32
    float* out = (float*)d_out;                // (32, 626, 128) f32

    prep_tw_kernel<<<1, 256>>>();
    prep_fb_kernel<<<NMELS, 32>>>(fb);
    fft_mel_kernel<<<dim3(NBLK, BATCH), 256>>>(x);
    pcen_part1_kernel<<<dim3(BATCH, KCH - 1), 128>>>();
    pcen_part2_kernel<<<dim3(BATCH, KCH), 128>>>(out);
}

// round 15
// speedup vs baseline: 3.0976x; 1.0491x over previous
#include <cuda_runtime.h>
#include <math.h>

#define N_FFT   1024
#define HOP     256
#define NBINS   513
#define NMELS   128
#define BATCH   32
#define SIGLEN  160000
#define PAD     512
#define NFRAMES 626
#define NPAIRS  313
#define NBLK    79
#define SUP     26

#define KCH     32
#define LCH     20
#define EMA_A   0.975f
#define EMA_S   0.025f

#define PADI(i) ((i) + ((i) >> 4))   // anti-conflict padding (float2 units)
#define FSZ2    1088                 // float2 slots per FFT unit

#define UNIT_BAR(q) asm volatile("bar.sync %0, %1;" :: "r"((q) + 1), "r"(64) : "memory")

// ---------------- device scratch ----------------
__device__ float  g_mel[BATCH * NFRAMES * NMELS];
__device__ float  g_T  [BATCH * KCH * NMELS];
__device__ float  g_fbT[SUP * NMELS];
__device__ int    g_start[NMELS];
__device__ int    g_len[NMELS];
__device__ float2 g_tw[256];         // W^k, k<256

// ---------------- prep: fb compaction + twiddles (one launch) -----------
__global__ void prep_kernel(const float* __restrict__ fb) {
    const int m    = blockIdx.x;     // 0..127
    const int lane = threadIdx.x;    // 0..31

    // blocks 0..7 also fill the twiddle table (32 entries each)
    if (m < 8) {
        int k = m * 32 + lane;
        float ang = -6.283185307179586f * (float)k / (float)N_FFT;
        float s, c;
        sincosf(ang, &s, &c);
        g_tw[k] = make_float2(c, s);
    }

    int first = 0x7fffffff, last = -1;
    for (int f = lane; f < NBINS; f += 32) {
        float v = fb[f * NMELS + m];
        if (v != 0.0f) { first = min(first, f); last = max(last, f); }
    }
    first = __reduce_min_sync(0xffffffffu, first);
    last  = __reduce_max_sync(0xffffffffu, last);

    int st  = (last < 0) ? 0 : first;
    int len = (last < 0) ? 0 : (last - first + 1);
    if (len > SUP) len = SUP;

    if (lane == 0) { g_start[m] = st; g_len[m] = len; }
    if (lane < SUP) {
        int j = lane;
        g_fbT[j * NMELS + m] = (j < len) ? fb[(st + j) * NMELS + m] : 0.0f;
    }
}

__device__ __forceinline__ int reflect_idx(int src) {
    if (src < 0) src = -src;
    if (src >= SIGLEN) src = 2 * SIGLEN - 2 - src;
    return src;
}

__device__ __forceinline__ int rev8(int v) {
    int r = __brev(v) >> 24;
    return ((r & 0x55) << 1) | ((r & 0xAA) >> 1);
}

#define R4BFLY(x0r,x0i,x1r,x1i,x2r,x2i,x3r,x3i,                          \
               y0r,y0i,y1r,y1i,y2r,y2i,y3r,y3i)                          \
    {                                                                     \
        float t0r = (x0r)+(x2r), t0i = (x0i)+(x2i);                       \
        float t1r = (x0r)-(x2r), t1i = (x0i)-(x2i);                       \
        float t2r = (x1r)+(x3r), t2i = (x1i)+(x3i);                       \
        float t3r = (x1r)-(x3r), t3i = (x1i)-(x3i);                       \
        y0r = t0r + t2r;  y0i = t0i + t2i;                                \
        y1r = t1r + t3i;  y1i = t1i - t3r;                                \
        y2r = t0r - t2r;  y2i = t0i - t2i;                                \
        y3r = t1r - t3i;  y3i = t1i + t3r;                                \
    }

#define TWSET(w1, w2, w3)                                                 \
    float2 w2 = make_float2(w1.x*w1.x - w1.y*w1.y, 2.0f*w1.x*w1.y);       \
    float2 w3 = make_float2(w1.x*w2.x - w1.y*w2.y, w1.x*w2.y + w1.y*w2.x);

__device__ __forceinline__ float2 packmag(float2 Z1, float2 Z2) {
    float ar = 0.5f * (Z1.x + Z2.x);
    float ai = 0.5f * (Z1.y - Z2.y);
    float br = 0.5f * (Z1.y + Z2.y);
    float bi = 0.5f * (Z2.x - Z1.x);
    return make_float2(sqrtf(ar * ar + ai * ai), sqrtf(br * br + bi * bi));
}

// ---------------- fft + mel ----------------------------------------------
__global__ __launch_bounds__(256, 4)
void fft_mel_kernel(const float* __restrict__ x) {
    __shared__ float2 cv[4 * FSZ2];      // 34.8 KB

    const int tid = threadIdx.x;
    const int q   = tid >> 6;            // FFT unit 0..3
    const int t   = tid & 63;
    const int b   = blockIdx.y;
    const int p0  = blockIdx.x * 4 + q;
    const int pr  = min(p0, NPAIRS - 1);

    const float* xb = x + (size_t)b * SIGLEN;
    float2* mcv = cv + q * FSZ2;

    // ---- pass A source: straight from gmem into registers --------------
    const int baseA = 2 * pr * HOP - PAD;
    const int baseB = baseA + HOP;
    float xr[4][4], xi[4][4];
    if (pr >= 1 && pr <= 310) {
        #pragma unroll
        for (int a = 0; a < 4; a++)
            #pragma unroll
            for (int bb = 0; bb < 4; bb++) {
                int n = t + 64 * bb + 256 * a;
                xr[a][bb] = xb[baseA + n];
                xi[a][bb] = xb[baseB + n];
            }
    } else {
        #pragma unroll
        for (int a = 0; a < 4; a++)
            #pragma unroll
            for (int bb = 0; bb < 4; bb++) {
                int n = t + 64 * bb + 256 * a;
                xr[a][bb] = xb[reflect_idx(baseA + n)];
                xi[a][bb] = xb[reflect_idx(baseB + n)];
            }
    }

    // ================= PASS A: stages S=256 (a), S=64 (b) ===============
    #pragma unroll
    for (int bb = 0; bb < 4; bb++) {
        float y0r,y0i,y1r,y1i,y2r,y2i,y3r,y3i;
        R4BFLY(xr[0][bb],xi[0][bb], xr[1][bb],xi[1][bb],
               xr[2][bb],xi[2][bb], xr[3][bb],xi[3][bb],
               y0r,y0i,y1r,y1i,y2r,y2i,y3r,y3i);
        float2 w1 = __ldg(&g_tw[t + 64 * bb]);
        TWSET(w1, w2, w3);
        xr[0][bb] = y0r;                      xi[0][bb] = y0i;
        xr[1][bb] = y1r*w1.x - y1i*w1.y;      xi[1][bb] = y1r*w1.y + y1i*w1.x;
        xr[2][bb] = y2r*w2.x - y2i*w2.y;      xi[2][bb] = y2r*w2.y + y2i*w2.x;
        xr[3][bb] = y3r*w3.x - y3i*w3.y;      xi[3][bb] = y3r*w3.y + y3i*w3.x;
    }
    {
        float2 w1 = __ldg(&g_tw[4 * t]);
        TWSET(w1, w2, w3);
        #pragma unroll
        for (int a = 0; a < 4; a++) {
            float y0r,y0i,y1r,y1i,y2r,y2i,y3r,y3i;
            R4BFLY(xr[a][0],xi[a][0], xr[a][1],xi[a][1],
                   xr[a][2],xi[a][2], xr[a][3],xi[a][3],
                   y0r,y0i,y1r,y1i,y2r,y2i,y3r,y3i);
            xr[a][0] = y0r;                   xi[a][0] = y0i;
            xr[a][1] = y1r*w1.x - y1i*w1.y;   xi[a][1] = y1r*w1.y + y1i*w1.x;
            xr[a][2] = y2r*w2.x - y2i*w2.y;   xi[a][2] = y2r*w2.y + y2i*w2.x;
            xr[a][3] = y3r*w3.x - y3i*w3.y;   xi[a][3] = y3r*w3.y + y3i*w3.x;
        }
    }
    #pragma unroll
    for (int a = 0; a < 4; a++)
        #pragma unroll
        for (int bb = 0; bb < 4; bb++)
            mcv[PADI(t + 64 * bb + 256 * a)] = make_float2(xr[a][bb], xi[a][bb]);
    UNIT_BAR(q);

    // ================= PASS B: stages S=16 (c), S=4 (d) =================
    {
        const int d4 = t >> 4, d3 = (t >> 2) & 3, d0 = t & 3;
        const int base = 256 * d4 + 64 * d3 + d0;
        #pragma unroll
        for (int c = 0; c < 4; c++)
            #pragma unroll
            for (int d = 0; d < 4; d++) {
                float2 v = mcv[PADI(base + 16 * c + 4 * d)];
                xr[c][d] = v.x;  xi[c][d] = v.y;
            }
        #pragma unroll
        for (int d = 0; d < 4; d++) {
            float y0r,y0i,y1r,y1i,y2r,y2i,y3r,y3i;
            R4BFLY(xr[0][d],xi[0][d], xr[1][d],xi[1][d],
                   xr[2][d],xi[2][d], xr[3][d],xi[3][d],
                   y0r,y0i,y1r,y1i,y2r,y2i,y3r,y3i);
            float2 w1 = __ldg(&g_tw[16 * (d0 + 4 * d)]);
            TWSET(w1, w2, w3);
            xr[0][d] = y0r;                   xi[0][d] = y0i;
            xr[1][d] = y1r*w1.x - y1i*w1.y;   xi[1][d] = y1r*w1.y + y1i*w1.x;
            xr[2][d] = y2r*w2.x - y2i*w2.y;   xi[2][d] = y2r*w2.y + y2i*w2.x;
            xr[3][d] = y3r*w3.x - y3i*w3.y;   xi[3][d] = y3r*w3.y + y3i*w3.x;
        }
        {
            float2 w1 = __ldg(&g_tw[64 * d0]);
            TWSET(w1, w2, w3);
            #pragma unroll
            for (int c = 0; c < 4; c++) {
                float y0r,y0i,y1r,y1i,y2r,y2i,y3r,y3i;
                R4BFLY(xr[c][0],xi[c][0], xr[c][1],xi[c][1],
                       xr[c][2],xi[c][2], xr[c][3],xi[c][3],
                       y0r,y0i,y1r,y1i,y2r,y2i,y3r,y3i);
                xr[c][0] = y0r;                   xi[c][0] = y0i;
                xr[c][1] = y1r*w1.x - y1i*w1.y;   xi[c][1] = y1r*w1.y + y1i*w1.x;
                xr[c][2] = y2r*w2.x - y2i*w2.y;   xi[c][2] = y2r*w2.y + y2i*w2.x;
                xr[c][3] = y3r*w3.x - y3i*w3.y;   xi[c][3] = y3r*w3.y + y3i*w3.x;
            }
        }
        #pragma unroll
        for (int c = 0; c < 4; c++)
            #pragma unroll
            for (int d = 0; d < 4; d++)
                mcv[PADI(base + 16 * c + 4 * d)] = make_float2(xr[c][d], xi[c][d]);
    }
    UNIT_BAR(q);

    // ===== FUSED last stage (S=1) + conjugate unpack =====================
    // prefetch mel metadata before the rendezvous
    const int m_pf   = tid & (NMELS - 1);
    const int st_pf  = g_start[m_pf];
    const int len_pf = g_len[m_pf];

    float2 mag1[4], mag2[4], mag0[3];
    const int v1 = t + 1, v2 = t + 65;
    #pragma unroll
    for (int task = 0; task < 2; task++) {
        const int v  = task ? v2 : v1;
        const int u  = rev8(v & 255);
        const int u2 = rev8((256 - v) & 255);
        float2 a0 = mcv[PADI(4*u)],   a1 = mcv[PADI(4*u+1)];
        float2 a2 = mcv[PADI(4*u+2)], a3 = mcv[PADI(4*u+3)];
        float G0r,G0i,G1r,G1i,G2r,G2i,G3r,G3i;
        R4BFLY(a0.x,a0.y, a1.x,a1.y, a2.x,a2.y, a3.x,a3.y,
               G0r,G0i,G1r,G1i,G2r,G2i,G3r,G3i);
        float2 b0 = mcv[PADI(4*u2)],   b1 = mcv[PADI(4*u2+1)];
        float2 b2 = mcv[PADI(4*u2+2)], b3 = mcv[PADI(4*u2+3)];
        float H0r,H0i,H1r,H1i,H2r,H2i,H3r,H3i;
        R4BFLY(b0.x,b0.y, b1.x,b1.y, b2.x,b2.y, b3.x,b3.y,
               H0r,H0i,H1r,H1i,H2r,H2i,H3r,H3i);
        float2* mg = task ? mag2 : mag1;
        mg[0] = packmag(make_float2(G0r,G0i), make_float2(H3r,H3i));
        mg[1] = packmag(make_float2(H0r,H0i), make_float2(G3r,G3i));
        mg[2] = packmag(make_float2(G1r,G1i), make_float2(H2r,H2i));
        mg[3] = packmag(make_float2(H1r,H1i), make_float2(G2r,G2i));
    }
    if (t == 0) {
        float2 a0 = mcv[PADI(0)], a1 = mcv[PADI(1)];
        float2 a2 = mcv[PADI(2)], a3 = mcv[PADI(3)];
        float G0r,G0i,G1r,G1i,G2r,G2i,G3r,G3i;
        R4BFLY(a0.x,a0.y, a1.x,a1.y, a2.x,a2.y, a3.x,a3.y,
               G0r,G0i,G1r,G1i,G2r,G2i,G3r,G3i);
        mag0[0] = packmag(make_float2(G0r,G0i), make_float2(G0r,G0i));
        mag0[1] = packmag(make_float2(G1r,G1i), make_float2(G3r,G3i));
        mag0[2] = packmag(make_float2(G2r,G2i), make_float2(G2r,G2i));
    }
    UNIT_BAR(q);   // unit's pass-B reads done before spec overlay

    {
        float2* sq = cv + q * FSZ2;
        sq[v1]       = mag1[0];
        sq[256 - v1] = mag1[1];
        sq[256 + v1] = mag1[2];
        sq[512 - v1] = mag1[3];
        sq[v2]       = mag2[0];
        sq[256 - v2] = mag2[1];
        sq[256 + v2] = mag2[2];
        sq[512 - v2] = mag2[3];
        if (t == 0) { sq[0] = mag0[0]; sq[256] = mag0[1]; sq[512] = mag0[2]; }
        if (t < SUP) sq[NBINS + t] = make_float2(0.0f, 0.0f);
    }
    __syncthreads();   // block-wide: mel reads across all units

    // ---- sparse mel: exact support length per mel -----------------------
    {
        const int m   = m_pf;
        const int h   = tid >> 7;
        const int st  = st_pf;
        const int len = len_pf;
        const float2* s0 = cv + (2 * h)     * FSZ2 + st;
        const float2* s1 = cv + (2 * h + 1) * FSZ2 + st;
        float a0 = 0.0f, b0 = 0.0f, a1 = 0.0f, b1 = 0.0f;
        #pragma unroll 2
        for (int j = 0; j < len; j++) {
            float fv = g_fbT[j * NMELS + m];
            float2 v0 = s0[j], v1f = s1[j];
            a0 = fmaf(v0.x,  fv, a0);  b0 = fmaf(v0.y,  fv, b0);
            a1 = fmaf(v1f.x, fv, a1);  b1 = fmaf(v1f.y, fv, b1);
        }
        const int pbase = blockIdx.x * 4;
        int fr0 = 2 * (pbase + 2 * h);
        int fr1 = 2 * (pbase + 2 * h + 1);
        size_t rowb = (size_t)b * NFRAMES;
        if (fr0 < NFRAMES)     g_mel[(rowb + fr0)     * NMELS + m] = a0;
        if (fr0 + 1 < NFRAMES) g_mel[(rowb + fr0 + 1) * NMELS + m] = b0;
        if (fr1 < NFRAMES)     g_mel[(rowb + fr1)     * NMELS + m] = a1;
        if (fr1 + 1 < NFRAMES) g_mel[(rowb + fr1 + 1) * NMELS + m] = b1;
    }
}

// ---------------- PCEN stage 1: per-chunk partial EMA -------------------
__global__ __launch_bounds__(128)
void pcen_part1_kernel() {
    const int m = threadIdx.x;
    const int b = blockIdx.x;
    const int c = blockIdx.y;

    const float* p = g_mel + ((size_t)b * NFRAMES + c * LCH) * NMELS + m;

    float state;
    if (c == 0) {
        state = p[0];
        #pragma unroll
        for (int t = 1; t < LCH; t++) {
            float v = p[(size_t)t * NMELS];
            state = fmaf(EMA_A, state, EMA_S * v);
        }
    } else {
        state = 0.0f;
        #pragma unroll
        for (int t = 0; t < LCH; t++) {
            float v = p[(size_t)t * NMELS];
            state = fmaf(EMA_A, state, EMA_S * v);
        }
    }
    g_T[((size_t)b * KCH + c) * NMELS + m] = state;
}

// ---------------- PCEN stage 2: outputs (prefix inline) -----------------
__device__ __forceinline__ float pcen_f(float v, float M) {
    float pw = exp2f(-0.98f * __log2f(M + 1e-6f));
    float y  = fmaf(v, pw, 2.0f);
    return y * rsqrtf(y) - 1.41421356237309515f;
}

__global__ __launch_bounds__(128)
void pcen_part2_kernel(float* __restrict__ out) {
    const int m = threadIdx.x;
    const int b = blockIdx.x;
    const int c = blockIdx.y;

    const int t0 = c * LCH;
    const float* p = g_mel + ((size_t)b * NFRAMES + t0) * NMELS + m;
    float*       o = out  + ((size_t)b * NFRAMES + t0) * NMELS + m;

    if (c == 0) {
        float v0 = p[0];
        float state = v0;
        o[0] = pcen_f(v0, state);
        #pragma unroll
        for (int t = 1; t < LCH; t++) {
            float v = p[(size_t)t * NMELS];
            state = fmaf(EMA_A, state, EMA_S * v);
            o[(size_t)t * NMELS] = pcen_f(v, state);
        }
        return;
    }

    float A = 1.0f;
    #pragma unroll
    for (int i = 0; i < LCH; i++) A *= EMA_A;

    // prefix over g_T[0..c-1], unrolled x4 for MLP
    float state = 0.0f;
    const float* Tp = g_T + (size_t)b * KCH * NMELS + m;
    {
        float A2 = A * A, A4 = A2 * A2;
        int cc = 0;
        for (; cc + 4 <= c; cc += 4) {
            float t0v = Tp[(size_t)(cc)     * NMELS];
            float t1v = Tp[(size_t)(cc + 1) * NMELS];
            float t2v = Tp[(size_t)(cc + 2) * NMELS];
            float t3v = Tp[(size_t)(cc + 3) * NMELS];
            float s = fmaf(A, t0v, t1v);      // A*t0 + t1
            s = fmaf(A, s, t2v);
            s = fmaf(A, s, t3v);
            state = fmaf(A4, state, s);
        }
        for (; cc < c; cc++)
            state = fmaf(A, state, Tp[(size_t)cc * NMELS]);
    }

    if (c < KCH - 1) {
        #pragma unroll
        for (int t = 0; t < LCH; t++) {
            float v = p[(size_t)t * NMELS];
            state = fmaf(EMA_A, state, EMA_S * v);
            o[(size_t)t * NMELS] = pcen_f(v, state);
        }
    } else {
        #pragma unroll
        for (int t = 0; t < NFRAMES - (KCH - 1) * LCH; t++) {
            float v = p[(size_t)t * NMELS];
            state = fmaf(EMA_A, state, EMA_S * v);
            o[(size_t)t * NMELS] = pcen_f(v, state);
        }
    }
}

// ---------------- launch ----------------
extern "C" void kernel_launch(void* const* d_in, const int* in_sizes, int n_in,
                              void* d_out, int out_size) {
    const float* x  = (const float*)d_in[0];   // (32, 160000) f32
    const float* fb = (const float*)d_in[1];   // (513, 128)  f32
    float* out = (float*)d_out;                // (32, 626, 128) f32

    prep_kernel<<<NMELS, 32>>>(fb);
    fft_mel_kernel<<<dim3(NBLK, BATCH), 256>>>(x);
    pcen_part1_kernel<<<dim3(BATCH, KCH - 1), 128>>>();
    pcen_part2_kernel<<<dim3(BATCH, KCH), 128>>>(out);
}

// round 16
// speedup vs baseline: 3.1504x; 1.0171x over previous
#include <cuda_runtime.h>
#include <math.h>

#define N_FFT   1024
#define HOP     256
#define NBINS   513
#define NMELS   128
#define BATCH   32
#define SIGLEN  160000
#define PAD     512
#define NFRAMES 626
#define NPAIRS  313
#define NBLK    79
#define SUP     26

#define KCH     32
#define LCH     20
#define EMA_A   0.975f
#define EMA_S   0.025f

#define PADI(i) ((i) + ((i) >> 4))
#define FSZ2    1088

#define UNIT_BAR(q) asm volatile("bar.sync %0, %1;" :: "r"((q) + 1), "r"(64) : "memory")

// ---------------- device scratch ----------------
__device__ float  g_mel[BATCH * NFRAMES * NMELS];
__device__ float  g_T  [BATCH * KCH * NMELS];
__device__ float  g_fbT[SUP * NMELS];
__device__ int    g_start[NMELS];
__device__ int    g_len[NMELS];
__device__ float2 g_tw[256];

// ---------------- prep ----------------
__global__ void prep_kernel(const float* __restrict__ fb) {
    const int m    = blockIdx.x;
    const int lane = threadIdx.x;

    if (m < 8) {
        int k = m * 32 + lane;
        float ang = -6.283185307179586f * (float)k / (float)N_FFT;
        float s, c;
        sincosf(ang, &s, &c);
        g_tw[k] = make_float2(c, s);
    }

    int first = 0x7fffffff, last = -1;
    for (int f = lane; f < NBINS; f += 32) {
        float v = fb[f * NMELS + m];
        if (v != 0.0f) { first = min(first, f); last = max(last, f); }
    }
    first = __reduce_min_sync(0xffffffffu, first);
    last  = __reduce_max_sync(0xffffffffu, last);

    int st  = (last < 0) ? 0 : first;
    int len = (last < 0) ? 0 : (last - first + 1);
    if (len > SUP) len = SUP;

    if (lane == 0) { g_start[m] = st; g_len[m] = len; }
    if (lane < SUP) {
        int j = lane;
        g_fbT[j * NMELS + m] = (j < len) ? fb[(st + j) * NMELS + m] : 0.0f;
    }
}

__device__ __forceinline__ int reflect_idx(int src) {
    if (src < 0) src = -src;
    if (src >= SIGLEN) src = 2 * SIGLEN - 2 - src;
    return src;
}

__device__ __forceinline__ int rev8(int v) {
    int r = __brev(v) >> 24;
    return ((r & 0x55) << 1) | ((r & 0xAA) >> 1);
}

// ---------------- f32x2 packed complex primitives (sm_103a) --------------
__device__ __forceinline__ float2 f2add(float2 a, float2 b) {
    float2 r;
    asm("{.reg .b64 x,y,z;\n\t"
        "mov.b64 x,{%2,%3};\n\t"
        "mov.b64 y,{%4,%5};\n\t"
        "add.rn.f32x2 z,x,y;\n\t"
        "mov.b64 {%0,%1},z;}"
        : "=f"(r.x), "=f"(r.y)
        : "f"(a.x), "f"(a.y), "f"(b.x), "f"(b.y));
    return r;
}
__device__ __forceinline__ float2 f2sub(float2 a, float2 b) {
    float2 r;
    asm("{.reg .b64 x,y,z;\n\t"
        "mov.b64 x,{%2,%3};\n\t"
        "mov.b64 y,{%4,%5};\n\t"
        "sub.rn.f32x2 z,x,y;\n\t"
        "mov.b64 {%0,%1},z;}"
        : "=f"(r.x), "=f"(r.y)
        : "f"(a.x), "f"(a.y), "f"(b.x), "f"(b.y));
    return r;
}
// complex multiply v*w: w=(wx,wy), wn=(-wy,wx); = (vx,vx)*w + (vy,vy)*wn
__device__ __forceinline__ float2 f2cmul(float2 v, float2 w, float2 wn) {
    float2 r;
    asm("{.reg .b64 a,b,c,d;\n\t"
        "mov.b64 a,{%2,%2};\n\t"
        "mov.b64 b,{%4,%5};\n\t"
        "mov.b64 c,{%3,%3};\n\t"
        "mov.b64 d,{%6,%7};\n\t"
        "mul.rn.f32x2 c,c,d;\n\t"
        "fma.rn.f32x2 a,a,b,c;\n\t"
        "mov.b64 {%0,%1},a;}"
        : "=f"(r.x), "=f"(r.y)
        : "f"(v.x), "f"(v.y), "f"(w.x), "f"(w.y), "f"(wn.x), "f"(wn.y));
    return r;
}

// packed radix-4 DIF butterfly: Y0..Y3 from A,B,C,D
#define R4BFLY2(A,B,C,D, Y0,Y1,Y2,Y3)                                    \
    {                                                                     \
        float2 T0 = f2add(A, C), T1 = f2sub(A, C);                        \
        float2 T2 = f2add(B, D), T3 = f2sub(B, D);                        \
        float2 T3s = make_float2(T3.y, -T3.x);                            \
        Y0 = f2add(T0, T2);  Y2 = f2sub(T0, T2);                          \
        Y1 = f2add(T1, T3s); Y3 = f2sub(T1, T3s);                         \
    }

#define TWSET(w1, w2, w3)                                                 \
    float2 w2 = make_float2(w1.x*w1.x - w1.y*w1.y, 2.0f*w1.x*w1.y);       \
    float2 w3 = make_float2(w1.x*w2.x - w1.y*w2.y, w1.x*w2.y + w1.y*w2.x);
#define NEGSWAP(w) make_float2(-(w).y, (w).x)

__device__ __forceinline__ float2 packmag(float2 Z1, float2 Z2) {
    float ar = 0.5f * (Z1.x + Z2.x);
    float ai = 0.5f * (Z1.y - Z2.y);
    float br = 0.5f * (Z1.y + Z2.y);
    float bi = 0.5f * (Z2.x - Z1.x);
    return make_float2(sqrtf(ar * ar + ai * ai), sqrtf(br * br + bi * bi));
}

// ---------------- fft + mel ----------------------------------------------
__global__ __launch_bounds__(256, 4)
void fft_mel_kernel(const float* __restrict__ x) {
    __shared__ float2 cv[4 * FSZ2];

    const int tid = threadIdx.x;
    const int q   = tid >> 6;
    const int t   = tid & 63;
    const int b   = blockIdx.y;
    const int p0  = blockIdx.x * 4 + q;
    const int pr  = min(p0, NPAIRS - 1);

    const float* xb = x + (size_t)b * SIGLEN;
    float2* mcv = cv + q * FSZ2;

    // ---- pass A source: gmem -> registers -------------------------------
    const int baseA = 2 * pr * HOP - PAD;
    const int baseB = baseA + HOP;
    float2 xv[4][4];
    if (pr >= 1 && pr <= 310) {
        #pragma unroll
        for (int a = 0; a < 4; a++)
            #pragma unroll
            for (int bb = 0; bb < 4; bb++) {
                int n = t + 64 * bb + 256 * a;
                xv[a][bb] = make_float2(xb[baseA + n], xb[baseB + n]);
            }
    } else {
        #pragma unroll
        for (int a = 0; a < 4; a++)
            #pragma unroll
            for (int bb = 0; bb < 4; bb++) {
                int n = t + 64 * bb + 256 * a;
                xv[a][bb] = make_float2(xb[reflect_idx(baseA + n)],
                                        xb[reflect_idx(baseB + n)]);
            }
    }

    // ================= PASS A: stages S=256 (a), S=64 (b) ===============
    #pragma unroll
    for (int bb = 0; bb < 4; bb++) {
        float2 y0, y1, y2, y3;
        R4BFLY2(xv[0][bb], xv[1][bb], xv[2][bb], xv[3][bb], y0, y1, y2, y3);
        float2 w1 = __ldg(&g_tw[t + 64 * bb]);
        TWSET(w1, w2, w3);
        xv[0][bb] = y0;
        xv[1][bb] = f2cmul(y1, w1, NEGSWAP(w1));
        xv[2][bb] = f2cmul(y2, w2, NEGSWAP(w2));
        xv[3][bb] = f2cmul(y3, w3, NEGSWAP(w3));
    }
    {
        float2 w1 = __ldg(&g_tw[4 * t]);
        TWSET(w1, w2, w3);
        float2 w1n = NEGSWAP(w1), w2n = NEGSWAP(w2), w3n = NEGSWAP(w3);
        #pragma unroll
        for (int a = 0; a < 4; a++) {
            float2 y0, y1, y2, y3;
            R4BFLY2(xv[a][0], xv[a][1], xv[a][2], xv[a][3], y0, y1, y2, y3);
            xv[a][0] = y0;
            xv[a][1] = f2cmul(y1, w1, w1n);
            xv[a][2] = f2cmul(y2, w2, w2n);
            xv[a][3] = f2cmul(y3, w3, w3n);
        }
    }
    #pragma unroll
    for (int a = 0; a < 4; a++)
        #pragma unroll
        for (int bb = 0; bb < 4; bb++)
            mcv[PADI(t + 64 * bb + 256 * a)] = xv[a][bb];
    UNIT_BAR(q);

    // ================= PASS B: stages S=16 (c), S=4 (d) =================
    {
        const int d4 = t >> 4, d3 = (t >> 2) & 3, d0 = t & 3;
        const int base = 256 * d4 + 64 * d3 + d0;
        #pragma unroll
        for (int c = 0; c < 4; c++)
            #pragma unroll
            for (int d = 0; d < 4; d++)
                xv[c][d] = mcv[PADI(base + 16 * c + 4 * d)];
        #pragma unroll
        for (int d = 0; d < 4; d++) {
            float2 y0, y1, y2, y3;
            R4BFLY2(xv[0][d], xv[1][d], xv[2][d], xv[3][d], y0, y1, y2, y3);
            float2 w1 = __ldg(&g_tw[16 * (d0 + 4 * d)]);
            TWSET(w1, w2, w3);
            xv[0][d] = y0;
            xv[1][d] = f2cmul(y1, w1, NEGSWAP(w1));
            xv[2][d] = f2cmul(y2, w2, NEGSWAP(w2));
            xv[3][d] = f2cmul(y3, w3, NEGSWAP(w3));
        }
        {
            float2 w1 = __ldg(&g_tw[64 * d0]);
            TWSET(w1, w2, w3);
            float2 w1n = NEGSWAP(w1), w2n = NEGSWAP(w2), w3n = NEGSWAP(w3);
            #pragma unroll
            for (int c = 0; c < 4; c++) {
                float2 y0, y1, y2, y3;
                R4BFLY2(xv[c][0], xv[c][1], xv[c][2], xv[c][3], y0, y1, y2, y3);
                xv[c][0] = y0;
                xv[c][1] = f2cmul(y1, w1, w1n);
                xv[c][2] = f2cmul(y2, w2, w2n);
                xv[c][3] = f2cmul(y3, w3, w3n);
            }
        }
        #pragma unroll
        for (int c = 0; c < 4; c++)
            #pragma unroll
            for (int d = 0; d < 4; d++)
                mcv[PADI(base + 16 * c + 4 * d)] = xv[c][d];
    }
    UNIT_BAR(q);

    // ===== FUSED last stage (S=1) + conjugate unpack =====================
    const int m_pf   = tid & (NMELS - 1);
    const int st_pf  = g_start[m_pf];
    const int len_pf = g_len[m_pf];

    float2 mag1[4], mag2[4], mag0[3];
    const int v1 = t + 1, v2 = t + 65;
    #pragma unroll
    for (int task = 0; task < 2; task++) {
        const int v  = task ? v2 : v1;
        const int u  = rev8(v & 255);
        const int u2 = rev8((256 - v) & 255);
        float2 a0 = mcv[PADI(4*u)],   a1 = mcv[PADI(4*u+1)];
        float2 a2 = mcv[PADI(4*u+2)], a3 = mcv[PADI(4*u+3)];
        float2 G0, G1, G2, G3;
        R4BFLY2(a0, a1, a2, a3, G0, G1, G2, G3);
        float2 b0 = mcv[PADI(4*u2)],   b1 = mcv[PADI(4*u2+1)];
        float2 b2 = mcv[PADI(4*u2+2)], b3 = mcv[PADI(4*u2+3)];
        float2 H0, H1, H2, H3;
        R4BFLY2(b0, b1, b2, b3, H0, H1, H2, H3);
        float2* mg = task ? mag2 : mag1;
        mg[0] = packmag(G0, H3);
        mg[1] = packmag(H0, G3);
        mg[2] = packmag(G1, H2);
        mg[3] = packmag(H1, G2);
    }
    if (t == 0) {
        float2 a0 = mcv[PADI(0)], a1 = mcv[PADI(1)];
        float2 a2 = mcv[PADI(2)], a3 = mcv[PADI(3)];
        float2 G0, G1, G2, G3;
        R4BFLY2(a0, a1, a2, a3, G0, G1, G2, G3);
        mag0[0] = packmag(G0, G0);
        mag0[1] = packmag(G1, G3);
        mag0[2] = packmag(G2, G2);
    }
    UNIT_BAR(q);

    {
        float2* sq = cv + q * FSZ2;
        sq[v1]       = mag1[0];
        sq[256 - v1] = mag1[1];
        sq[256 + v1] = mag1[2];
        sq[512 - v1] = mag1[3];
        sq[v2]       = mag2[0];
        sq[256 - v2] = mag2[1];
        sq[256 + v2] = mag2[2];
        sq[512 - v2] = mag2[3];
        if (t == 0) { sq[0] = mag0[0]; sq[256] = mag0[1]; sq[512] = mag0[2]; }
        if (t < SUP) sq[NBINS + t] = make_float2(0.0f, 0.0f);
    }
    __syncthreads();

    // ---- sparse mel ------------------------------------------------------
    {
        const int m   = m_pf;
        const int h   = tid >> 7;
        const int st  = st_pf;
        const int len = len_pf;
        const float2* s0 = cv + (2 * h)     * FSZ2 + st;
        const float2* s1 = cv + (2 * h + 1) * FSZ2 + st;
        float a0 = 0.0f, b0 = 0.0f, a1 = 0.0f, b1 = 0.0f;
        #pragma unroll 2
        for (int j = 0; j < len; j++) {
            float fv = g_fbT[j * NMELS + m];
            float2 v0 = s0[j], v1f = s1[j];
            a0 = fmaf(v0.x,  fv, a0);  b0 = fmaf(v0.y,  fv, b0);
            a1 = fmaf(v1f.x, fv, a1);  b1 = fmaf(v1f.y, fv, b1);
        }
        const int pbase = blockIdx.x * 4;
        int fr0 = 2 * (pbase + 2 * h);
        int fr1 = 2 * (pbase + 2 * h + 1);
        size_t rowb = (size_t)b * NFRAMES;
        if (fr0 < NFRAMES)     g_mel[(rowb + fr0)     * NMELS + m] = a0;
        if (fr0 + 1 < NFRAMES) g_mel[(rowb + fr0 + 1) * NMELS + m] = b0;
        if (fr1 < NFRAMES)     g_mel[(rowb + fr1)     * NMELS + m] = a1;
        if (fr1 + 1 < NFRAMES) g_mel[(rowb + fr1 + 1) * NMELS + m] = b1;
    }
}

// ---------------- PCEN stage 1 ----------------
__global__ __launch_bounds__(128)
void pcen_part1_kernel() {
    const int m = threadIdx.x;
    const int b = blockIdx.x;
    const int c = blockIdx.y;

    const float* p = g_mel + ((size_t)b * NFRAMES + c * LCH) * NMELS + m;

    float state;
    if (c == 0) {
        state = p[0];
        #pragma unroll
        for (int t = 1; t < LCH; t++) {
            float v = p[(size_t)t * NMELS];
            state = fmaf(EMA_A, state, EMA_S * v);
        }
    } else {
        state = 0.0f;
        #pragma unroll
        for (int t = 0; t < LCH; t++) {
            float v = p[(size_t)t * NMELS];
            state = fmaf(EMA_A, state, EMA_S * v);
        }
    }
    g_T[((size_t)b * KCH + c) * NMELS + m] = state;
}

// ---------------- PCEN stage 2 ----------------
__device__ __forceinline__ float pcen_f(float v, float M) {
    float pw = exp2f(-0.98f * __log2f(M + 1e-6f));
    float y  = fmaf(v, pw, 2.0f);
    return y * rsqrtf(y) - 1.41421356237309515f;
}

__global__ __launch_bounds__(128)
void pcen_part2_kernel(float* __restrict__ out) {
    const int m = threadIdx.x;
    const int b = blockIdx.x;
    const int c = blockIdx.y;

    const int t0 = c * LCH;
    const float* p = g_mel + ((size_t)b * NFRAMES + t0) * NMELS + m;
    float*       o = out  + ((size_t)b * NFRAMES + t0) * NMELS + m;

    if (c == 0) {
        float v0 = p[0];
        float state = v0;
        o[0] = pcen_f(v0, state);
        #pragma unroll
        for (int t = 1; t < LCH; t++) {
            float v = p[(size_t)t * NMELS];
            state = fmaf(EMA_A, state, EMA_S * v);
            o[(size_t)t * NMELS] = pcen_f(v, state);
        }
        return;
    }

    float A = 1.0f;
    #pragma unroll
    for (int i = 0; i < LCH; i++) A *= EMA_A;

    float state = 0.0f;
    const float* Tp = g_T + (size_t)b * KCH * NMELS + m;
    {
        float A2 = A * A, A4 = A2 * A2;
        int cc = 0;
        for (; cc + 4 <= c; cc += 4) {
            float t0v = Tp[(size_t)(cc)     * NMELS];
            float t1v = Tp[(size_t)(cc + 1) * NMELS];
            float t2v = Tp[(size_t)(cc + 2) * NMELS];
            float t3v = Tp[(size_t)(cc + 3) * NMELS];
            float s = fmaf(A, t0v, t1v);
            s = fmaf(A, s, t2v);
            s = fmaf(A, s, t3v);
            state = fmaf(A4, state, s);
        }
        for (; cc < c; cc++)
            state = fmaf(A, state, Tp[(size_t)cc * NMELS]);
    }

    if (c < KCH - 1) {
        #pragma unroll
        for (int t = 0; t < LCH; t++) {
            float v = p[(size_t)t * NMELS];
            state = fmaf(EMA_A, state, EMA_S * v);
            o[(size_t)t * NMELS] = pcen_f(v, state);
        }
    } else {
        #pragma unroll
        for (int t = 0; t < NFRAMES - (KCH - 1) * LCH; t++) {
            float v = p[(size_t)t * NMELS];
            state = fmaf(EMA_A, state, EMA_S * v);
            o[(size_t)t * NMELS] = pcen_f(v, state);
        }
    }
}

// ---------------- launch ----------------
extern "C" void kernel_launch(void* const* d_in, const int* in_sizes, int n_in,
                              void* d_out, int out_size) {
    const float* x  = (const float*)d_in[0];   // (32, 160000) f32
    const float* fb = (const float*)d_in[1];   // (513, 128)  f32
    float* out = (float*)d_out;                // (32, 626, 128) f32

    prep_kernel<<<NMELS, 32>>>(fb);
    fft_mel_kernel<<<dim3(NBLK, BATCH), 256>>>(x);
    pcen_part1_kernel<<<dim3(BATCH, KCH - 1), 128>>>();
    pcen_part2_kernel<<<dim3(BATCH, KCH), 128>>>(out);
}